// round 13
// baseline (speedup 1.0000x reference)
#include <cuda_runtime.h>
#include <cuda_fp16.h>
#include <cstdint>
#include <stdint.h>
#include <string.h>
#include <math.h>

// ---------------- problem constants ----------------
#define N_TOT   28800          // 8*36*100
#define K1      4608           // 512*9
#define M1      1024
#define K2      1024
#define M2      128
#define SEG_ELEMS (8*5*288*800)

// GEMM tiling: CTA 128m x 128n, K-chunk 32, double buffered, fp16 2-term
#define NCHUNK1 144
#define STG     24576          // Ahi 8K + Alo 8K + Bhi 8K
#define A_LO_OFF  8192
#define B_HI_OFF 16384
#define DSMEM1 (2*STG)
#define NCHUNK2 32
#define DSMEM2 (2*STG)

// ---------------- device scratch ----------------
__device__ __half g_w1h[M1 * K1];     // conv1a W hi [m][k'], k'=tap*512+c
__device__ __half g_w1l[M1 * K1];     // conv1a W lo
__device__ __half g_xt [N_TOT * 512]; // x transposed [n][c], single fp16
__device__ __half g_w2h[M2 * K2];     // conv1b W hi [m][k]
__device__ __half g_w2l[M2 * K2];
__device__ __half g_h1 [M1 * N_TOT];  // h1 [k][n], single fp16
__device__ __align__(16) unsigned char g_zerobuf[1024];
__device__ float g_h2 [M2 * N_TOT];   // [c][b][h][w]
__device__ float g_h2t[M2 * N_TOT];   // [c][b][w][h]
__device__ float g_h3[5 * N_TOT];
__device__ float g_p[8 * 4500];
// ---------------------------------------------------

// ================= PTX helpers =================
__device__ __forceinline__ uint32_t smem_u32(const void* p) {
    uint32_t a;
    asm("{ .reg .u64 t; cvta.to.shared.u64 t, %1; cvt.u32.u64 %0, t; }" : "=r"(a) : "l"(p));
    return a;
}
__device__ __forceinline__ void cp16(uint32_t dst, const void* src) {
    asm volatile("cp.async.cg.shared.global [%0], [%1], 16;" :: "r"(dst), "l"(src));
}
__device__ __forceinline__ void cp_commit() {
    asm volatile("cp.async.commit_group;");
}
template<int N> __device__ __forceinline__ void cp_wait() {
    asm volatile("cp.async.wait_group %0;" :: "n"(N) : "memory");
}
__device__ __forceinline__ void ldsm4(uint32_t addr, uint32_t r[4]) {
    asm volatile("ldmatrix.sync.aligned.m8n8.x4.shared.b16 {%0,%1,%2,%3}, [%4];"
                 : "=r"(r[0]), "=r"(r[1]), "=r"(r[2]), "=r"(r[3]) : "r"(addr));
}
__device__ __forceinline__ void ldsm4_t(uint32_t addr, uint32_t r[4]) {
    asm volatile("ldmatrix.sync.aligned.m8n8.x4.trans.shared.b16 {%0,%1,%2,%3}, [%4];"
                 : "=r"(r[0]), "=r"(r[1]), "=r"(r[2]), "=r"(r[3]) : "r"(addr));
}
__device__ __forceinline__ void mma16816(float c[4], const uint32_t a[4], uint32_t b0, uint32_t b1) {
    asm volatile("mma.sync.aligned.m16n8k16.row.col.f32.f16.f16.f32 "
                 "{%0,%1,%2,%3}, {%4,%5,%6,%7}, {%8,%9}, {%0,%1,%2,%3};"
                 : "+f"(c[0]), "+f"(c[1]), "+f"(c[2]), "+f"(c[3])
                 : "r"(a[0]), "r"(a[1]), "r"(a[2]), "r"(a[3]), "r"(b0), "r"(b1));
}
// packed f32x2 ops
#define PACKF2(dst, lo, hi) asm("mov.b64 %0, {%1, %2};" : "=l"(dst) : "f"(lo), "f"(hi))
#define FMAF2(acc, a, bq)   asm("fma.rn.f32x2 %0, %1, %2, %0;" : "+l"(acc) : "l"(a), "l"(bq))
#define UNPACKF2(lo, hi, s) asm("mov.b64 {%0, %1}, %2;" : "=f"(lo), "=f"(hi) : "l"(s))
__device__ __forceinline__ unsigned long long f2bits(float2 v) {
    unsigned long long u;
    memcpy(&u, &v, 8);
    return u;
}

// ================= weight pack: fp32 -> fp16 hi/lo =================
__global__ void pack_w_k(const float* __restrict__ w1a, const float* __restrict__ w1b) {
    int o = blockIdx.x * blockDim.x + threadIdx.x;
    if (o < M1 * K1) {
        int m = o / K1;
        int k = o - m * K1;
        int tap = k >> 9;
        int c = k & 511;
        float v = w1a[(m * 512 + c) * 9 + tap];
        __half h = __float2half_rn(v);
        g_w1h[o] = h;
        g_w1l[o] = __float2half_rn(v - __half2float(h));
    }
    if (o < M2 * K2) {
        float v = w1b[o];
        __half h = __float2half_rn(v);
        g_w2h[o] = h;
        g_w2l[o] = __float2half_rn(v - __half2float(h));
    }
}

// ================= x transpose: [b][c][hw] -> [n][c] fp16 =================
__global__ void transpose_k(const float* __restrict__ x) {
    __shared__ float t[32][65];
    int n0 = blockIdx.x * 32, c0 = blockIdx.y * 64;
    int tid = threadIdx.x;
#pragma unroll
    for (int i = 0; i < 8; i++) {
        int idx = tid + i * 256;
        int n_l = idx & 31, c_l = idx >> 5;
        int n = n0 + n_l;
        int b = n / 3600;
        int hw = n - b * 3600;
        t[n_l][c_l] = x[((size_t)(b * 512 + c0 + c_l)) * 3600 + hw];
    }
    __syncthreads();
#pragma unroll
    for (int i = 0; i < 8; i++) {
        int idx = tid + i * 256;
        int c_l = idx & 63, n_l = idx >> 6;
        g_xt[(size_t)(n0 + n_l) * 512 + c0 + c_l] = __float2half_rn(t[n_l][c_l]);
    }
}

// ================= conv1a: fp16 2-term implicit GEMM + BN1 + ReLU =================
// grid (225, 8); block 256 (8 warps: 4 m x 2 n); outputs h1 fp16
__global__ __launch_bounds__(256, 2)
void conv1a_mma(const float* __restrict__ bg, const float* __restrict__ bb,
                const float* __restrict__ bm, const float* __restrict__ bv) {
    extern __shared__ char dsm[];
    uint32_t dbase = smem_u32(dsm);

    int tid = threadIdx.x;
    int wid = tid >> 5;
    int lane = tid & 31;
    int n0 = blockIdx.x * 128;
    int m0 = blockIdx.y * 128;
    int wm = wid & 3;
    int wn = wid >> 2;

    int rA = tid >> 2;
    int gA = tid & 3;
    uint32_t dst1 = (uint32_t)(rA * 64 + ((gA ^ (rA & 3)) << 4));
    uint32_t dst2 = dst1 + 4096;

    const char* w1h_b = (const char*)g_w1h;
    const char* w1l_b = (const char*)g_w1l;
    size_t aoff1 = 2 * ((size_t)(m0 + rA) * K1 + gA * 8);
    size_t aoff2 = 2 * ((size_t)(m0 + rA + 64) * K1 + gA * 8);

    int nB1 = n0 + rA, nB2 = n0 + rA + 64;
    int b1 = nB1 / 3600, r1 = nB1 - b1 * 3600, h1_ = r1 / 100, w1_ = r1 - h1_ * 100;
    int b2 = nB2 / 3600, r2 = nB2 - b2 * 3600, h2_ = r2 / 100, w2_ = r2 - h2_ * 100;

    const char* bp1; const char* bp2;
    auto set_tap = [&](int tap) {
        int kh = tap / 3, kw = tap - kh * 3;
        int ih1 = h1_ + 4 * kh - 4, iw1 = w1_ + 4 * kw - 4;
        int ih2 = h2_ + 4 * kh - 4, iw2 = w2_ + 4 * kw - 4;
        bool v1 = ((unsigned)ih1 < 36u) && ((unsigned)iw1 < 100u);
        bool v2 = ((unsigned)ih2 < 36u) && ((unsigned)iw2 < 100u);
        size_t o1 = (size_t)(b1 * 3600 + ih1 * 100 + iw1) * 1024;
        size_t o2 = (size_t)(b2 * 3600 + ih2 * 100 + iw2) * 1024;
        bp1 = v1 ? (const char*)g_xt + o1 : (const char*)g_zerobuf;
        bp2 = v2 ? (const char*)g_xt + o2 : (const char*)g_zerobuf;
    };

    auto load_chunk = [&](int ch, int st) {
        uint32_t sb = dbase + st * STG;
        size_t k0b = (size_t)ch * 64;
        size_t cob = (size_t)(ch & 15) * 64 + gA * 16;
        cp16(sb + dst1, w1h_b + aoff1 + k0b);
        cp16(sb + dst2, w1h_b + aoff2 + k0b);
        cp16(sb + A_LO_OFF + dst1, w1l_b + aoff1 + k0b);
        cp16(sb + A_LO_OFF + dst2, w1l_b + aoff2 + k0b);
        cp16(sb + B_HI_OFF + dst1, bp1 + cob);
        cp16(sb + B_HI_OFF + dst2, bp2 + cob);
        cp_commit();
    };

    float acc[2][8][4];
#pragma unroll
    for (int f = 0; f < 2; f++)
#pragma unroll
        for (int nb = 0; nb < 8; nb++)
#pragma unroll
            for (int i = 0; i < 4; i++) acc[f][nb][i] = 0.f;

    int arow = wm * 32 + ((lane >> 3) & 1) * 8 + (lane & 7);
    int agl  = lane >> 4;
    int bnrow_base = wn * 64 + ((lane >> 4) & 1) * 8 + (lane & 7);
    int bgl = (lane >> 3) & 1;

    set_tap(0);
    load_chunk(0, 0);

    for (int ch = 0; ch < NCHUNK1; ch++) {
        int cur = ch & 1;
        if (ch + 1 < NCHUNK1) {
            if (((ch + 1) & 15) == 0) set_tap((ch + 1) >> 4);
            load_chunk(ch + 1, (ch + 1) & 1);
            cp_wait<1>();
        } else {
            cp_wait<0>();
        }
        __syncthreads();

        uint32_t sb = dbase + cur * STG;
#pragma unroll
        for (int s = 0; s < 2; s++) {
            uint32_t aH[2][4], aL[2][4];
#pragma unroll
            for (int f = 0; f < 2; f++) {
                int r = arow + f * 16;
                int g = 2 * s + agl;
                uint32_t off = (uint32_t)(r * 64 + ((g ^ (r & 3)) << 4));
                ldsm4(sb + off, aH[f]);
                ldsm4(sb + A_LO_OFF + off, aL[f]);
            }
            // q-pair processing; term-major => same-acc distance 8
#pragma unroll
            for (int qp = 0; qp < 2; qp++) {
                uint32_t bH[2][4];
#pragma unroll
                for (int j = 0; j < 2; j++) {
                    int nr = bnrow_base + (qp * 2 + j) * 16;
                    int g = 2 * s + bgl;
                    uint32_t off = (uint32_t)(nr * 64 + ((g ^ (nr & 3)) << 4));
                    ldsm4(sb + B_HI_OFF + off, bH[j]);
                }
                // term 1: aH x bH
#pragma unroll
                for (int j = 0; j < 2; j++) {
                    int q = qp * 2 + j;
#pragma unroll
                    for (int f = 0; f < 2; f++) {
                        mma16816(acc[f][2 * q],     aH[f], bH[j][0], bH[j][1]);
                        mma16816(acc[f][2 * q + 1], aH[f], bH[j][2], bH[j][3]);
                    }
                }
                // term 2: aL x bH
#pragma unroll
                for (int j = 0; j < 2; j++) {
                    int q = qp * 2 + j;
#pragma unroll
                    for (int f = 0; f < 2; f++) {
                        mma16816(acc[f][2 * q],     aL[f], bH[j][0], bH[j][1]);
                        mma16816(acc[f][2 * q + 1], aL[f], bH[j][2], bH[j][3]);
                    }
                }
            }
        }
        __syncthreads();
    }

    int row0 = lane >> 2;
    int colp = (lane & 3) * 2;
#pragma unroll
    for (int f = 0; f < 2; f++) {
        int mA = m0 + wm * 32 + f * 16 + row0;
        int mB = mA + 8;
        float sA = bg[mA] * rsqrtf(bv[mA] + 1e-5f);
        float hA = bb[mA] - bm[mA] * sA;
        float sB = bg[mB] * rsqrtf(bv[mB] + 1e-5f);
        float hB = bb[mB] - bm[mB] * sB;
#pragma unroll
        for (int nb = 0; nb < 8; nb++) {
            int n = n0 + wn * 64 + nb * 8 + colp;
            float oa0 = fmaxf(fmaf(acc[f][nb][0], sA, hA), 0.f);
            float oa1 = fmaxf(fmaf(acc[f][nb][1], sA, hA), 0.f);
            float ob0 = fmaxf(fmaf(acc[f][nb][2], sB, hB), 0.f);
            float ob1 = fmaxf(fmaf(acc[f][nb][3], sB, hB), 0.f);
            __half2 pa, pb2;
            pa.x = __float2half_rn(oa0); pa.y = __float2half_rn(oa1);
            pb2.x = __float2half_rn(ob0); pb2.y = __float2half_rn(ob1);
            *(__half2*)&g_h1[(size_t)mA * N_TOT + n] = pa;
            *(__half2*)&g_h1[(size_t)mB * N_TOT + n] = pb2;
        }
    }
}

// ================= conv1b: fp16 2-term GEMM + BN2 + ReLU =================
__global__ __launch_bounds__(256, 2)
void conv1b_mma(const float* __restrict__ bg, const float* __restrict__ bb,
                const float* __restrict__ bm, const float* __restrict__ bv) {
    extern __shared__ char dsm2[];
    uint32_t dbase = smem_u32(dsm2);

    int tid = threadIdx.x;
    int wid = tid >> 5;
    int lane = tid & 31;
    int n0 = blockIdx.x * 128;
    int wm = wid & 3;
    int wn = wid >> 2;

    int rA = tid >> 2;
    int gA = tid & 3;
    uint32_t adst1 = (uint32_t)(rA * 64 + ((gA ^ (rA & 3)) << 4));
    uint32_t adst2 = adst1 + 4096;
    const char* w2h_b = (const char*)g_w2h;
    const char* w2l_b = (const char*)g_w2l;
    size_t aoff1 = (size_t)rA * 2048 + gA * 16;
    size_t aoff2 = (size_t)(rA + 64) * 2048 + gA * 16;

    const char* h1_b = (const char*)g_h1;
    uint32_t bdst[2]; size_t bsrc[2];
#pragma unroll
    for (int i = 0; i < 2; i++) {
        int idx = tid + i * 256;
        int k = idx >> 4, g = idx & 15;
        bdst[i] = (uint32_t)((k << 8) + ((g ^ (k & 7)) << 4));
        bsrc[i] = ((size_t)k * N_TOT + n0 + g * 8) * 2;
    }

    auto load_chunk = [&](int ch, int st) {
        uint32_t sb = dbase + st * STG;
        size_t ak = (size_t)ch * 64;
        size_t bk = (size_t)ch * 32 * N_TOT * 2;
        cp16(sb + adst1, w2h_b + aoff1 + ak);
        cp16(sb + adst2, w2h_b + aoff2 + ak);
        cp16(sb + A_LO_OFF + adst1, w2l_b + aoff1 + ak);
        cp16(sb + A_LO_OFF + adst2, w2l_b + aoff2 + ak);
        cp16(sb + B_HI_OFF + bdst[0], h1_b + bk + bsrc[0]);
        cp16(sb + B_HI_OFF + bdst[1], h1_b + bk + bsrc[1]);
        cp_commit();
    };

    float acc[2][8][4];
#pragma unroll
    for (int f = 0; f < 2; f++)
#pragma unroll
        for (int nb = 0; nb < 8; nb++)
#pragma unroll
            for (int i = 0; i < 4; i++) acc[f][nb][i] = 0.f;

    int arow = wm * 32 + ((lane >> 3) & 1) * 8 + (lane & 7);
    int agl  = lane >> 4;
    int bt = lane >> 3;
    int bkrow_base = (bt & 1) * 8 + (lane & 7);
    int bnc_base = wn * 8 + (bt >> 1);

    load_chunk(0, 0);

    for (int ch = 0; ch < NCHUNK2; ch++) {
        int cur = ch & 1;
        if (ch + 1 < NCHUNK2) {
            load_chunk(ch + 1, (ch + 1) & 1);
            cp_wait<1>();
        } else {
            cp_wait<0>();
        }
        __syncthreads();

        uint32_t sb = dbase + cur * STG;
#pragma unroll
        for (int s = 0; s < 2; s++) {
            uint32_t aH[2][4], aL[2][4];
#pragma unroll
            for (int f = 0; f < 2; f++) {
                int r = arow + f * 16;
                int g = 2 * s + agl;
                uint32_t off = (uint32_t)(r * 64 + ((g ^ (r & 3)) << 4));
                ldsm4(sb + off, aH[f]);
                ldsm4(sb + A_LO_OFF + off, aL[f]);
            }
            // q-pair processing, term-major
#pragma unroll
            for (int qp = 0; qp < 2; qp++) {
                uint32_t bH[2][4];
#pragma unroll
                for (int j = 0; j < 2; j++) {
                    int q = qp * 2 + j;
                    int krow = s * 16 + bkrow_base;
                    int ncol = bnc_base + q * 2;
                    uint32_t off = (uint32_t)((krow << 8) + ((ncol ^ (krow & 7)) << 4));
                    ldsm4_t(sb + B_HI_OFF + off, bH[j]);
                }
#pragma unroll
                for (int j = 0; j < 2; j++) {
                    int q = qp * 2 + j;
#pragma unroll
                    for (int f = 0; f < 2; f++) {
                        mma16816(acc[f][2 * q],     aH[f], bH[j][0], bH[j][1]);
                        mma16816(acc[f][2 * q + 1], aH[f], bH[j][2], bH[j][3]);
                    }
                }
#pragma unroll
                for (int j = 0; j < 2; j++) {
                    int q = qp * 2 + j;
#pragma unroll
                    for (int f = 0; f < 2; f++) {
                        mma16816(acc[f][2 * q],     aL[f], bH[j][0], bH[j][1]);
                        mma16816(acc[f][2 * q + 1], aL[f], bH[j][2], bH[j][3]);
                    }
                }
            }
        }
        __syncthreads();
    }

    int row0 = lane >> 2;
    int colp = (lane & 3) * 2;
#pragma unroll
    for (int f = 0; f < 2; f++) {
        int mA = wm * 32 + f * 16 + row0;
        int mB = mA + 8;
        float sA = bg[mA] * rsqrtf(bv[mA] + 1e-5f);
        float hA = bb[mA] - bm[mA] * sA;
        float sB = bg[mB] * rsqrtf(bv[mB] + 1e-5f);
        float hB = bb[mB] - bm[mB] * sB;
        float* dA = &g_h2[(size_t)mA * N_TOT];
        float* dB = &g_h2[(size_t)mB * N_TOT];
#pragma unroll
        for (int nb = 0; nb < 8; nb++) {
            int n = n0 + wn * 64 + nb * 8 + colp;
            float2 oa, ob;
            oa.x = fmaxf(fmaf(acc[f][nb][0], sA, hA), 0.f);
            oa.y = fmaxf(fmaf(acc[f][nb][1], sA, hA), 0.f);
            ob.x = fmaxf(fmaf(acc[f][nb][2], sB, hB), 0.f);
            ob.y = fmaxf(fmaf(acc[f][nb][3], sB, hB), 0.f);
            *(float2*)&dA[n] = oa;
            *(float2*)&dB[n] = ob;
        }
    }
}

// ================= message passing =================
// w-scan step: float4 staging + FFMA2 compute; grid (8,16), block 256; smem 92160B
__global__ __launch_bounds__(256)
void step_w4(const float* __restrict__ wgt, int h_prev, int h_cur) {
    extern __shared__ float sm[];
    float* swgt = sm;            // 8 co x 128 ci x 9
    float* sbuf = sm + 9216;     // 128 ci x 108

    int tid = threadIdx.x;
    int lane = tid & 31, ty = tid >> 5;
    int b = blockIdx.x, cg = blockIdx.y;
    int co = cg * 8 + ty;

    const float* wsrc = wgt + cg * 8 * 1152;
    for (int i = tid; i < 9216; i += 256) swgt[i] = __ldg(&wsrc[i]);

    // float4 staging: 27 quads per ci; quad 0 (p=-4..-1) and quad 26 (p=100..103) are zeros
    const float* prevBase = g_h2 + b * 3600 + h_prev * 100;
    const float4 z4 = make_float4(0.f, 0.f, 0.f, 0.f);
    for (int idx = tid; idx < 128 * 27; idx += 256) {
        int ci = idx / 27;
        int q = idx - ci * 27;
        float4 v = z4;
        if (q >= 1 && q <= 25)
            v = *(const float4*)(prevBase + (size_t)ci * N_TOT + q * 4 - 4);
        *(float4*)(sbuf + ci * 108 + q * 4) = v;
    }
    __syncthreads();

    if (lane < 25) {
        int p0 = lane * 4;
        const float* sw = swgt + ty * 1152;
        unsigned long long acc01 = 0ull, acc23 = 0ull;
#pragma unroll 2
        for (int ci = 0; ci < 128; ci++) {
            const float2* s2 = (const float2*)(sbuf + ci * 108 + p0);
            float2 a0 = s2[0], a1 = s2[1], a2 = s2[2], a3 = s2[3], a4 = s2[4], a5 = s2[5];
            unsigned long long P[11];
            P[0] = f2bits(a0); P[2] = f2bits(a1); P[4] = f2bits(a2);
            P[6] = f2bits(a3); P[8] = f2bits(a4); P[10] = f2bits(a5);
            PACKF2(P[1], a0.y, a1.x);
            PACKF2(P[3], a1.y, a2.x);
            PACKF2(P[5], a2.y, a3.x);
            PACKF2(P[7], a3.y, a4.x);
            PACKF2(P[9], a4.y, a5.x);
            const float* wr = sw + ci * 9;
#pragma unroll
            for (int t = 0; t < 9; t++) {
                float wv = wr[t];
                unsigned long long W;
                PACKF2(W, wv, wv);
                FMAF2(acc01, W, P[t]);
                FMAF2(acc23, W, P[t + 2]);
            }
        }
        float o0, o1, o2, o3;
        UNPACKF2(o0, o1, acc01);
        UNPACKF2(o2, o3, acc23);
        float* cur = g_h2 + (size_t)co * N_TOT + b * 3600 + h_cur * 100 + p0;
        cur[0] += fmaxf(o0, 0.f);
        cur[1] += fmaxf(o1, 0.f);
        cur[2] += fmaxf(o2, 0.f);
        cur[3] += fmaxf(o3, 0.f);
    }
}

__global__ void transpose_h2() {
    __shared__ float sm[3600];
    int c = blockIdx.x, b = blockIdx.y;
    const float* src = g_h2 + (size_t)c * N_TOT + b * 3600;
    float* dst = g_h2t + (size_t)c * N_TOT + b * 3600;
    int tid = threadIdx.x;
    for (int i = tid; i < 3600; i += 256) sm[i] = src[i];
    __syncthreads();
    for (int j = tid; j < 3600; j += 256) {
        int w = j / 36, h = j - w * 36;
        dst[j] = sm[h * 100 + w];
    }
}

// h-scan step: float4 staging + FFMA2; grid (8,16), block 256; smem 61440B
__global__ __launch_bounds__(256)
void step_h4(const float* __restrict__ wgt, int w_prev, int w_cur) {
    extern __shared__ float sm[];
    float* swgt = sm;            // 8 co x 128 ci x 9
    float* sbuf = sm + 9216;     // 128 ci x 48 (44 used)

    int tid = threadIdx.x;
    int lane = tid & 31, ty = tid >> 5;
    int b = blockIdx.x, cg = blockIdx.y;
    int co = cg * 8 + ty;

    const float* wsrc = wgt + cg * 8 * 1152;
    for (int i = tid; i < 9216; i += 256) swgt[i] = __ldg(&wsrc[i]);

    // float4 staging: 11 quads per ci; quad 0 (p=-4..-1) and quad 10 (p=36..39) zeros
    const float* prevBase = g_h2t + b * 3600 + w_prev * 36;
    const float4 z4 = make_float4(0.f, 0.f, 0.f, 0.f);
    for (int idx = tid; idx < 128 * 11; idx += 256) {
        int ci = idx / 11;
        int q = idx - ci * 11;
        float4 v = z4;
        if (q >= 1 && q <= 9)
            v = *(const float4*)(prevBase + (size_t)ci * N_TOT + q * 4 - 4);
        *(float4*)(sbuf + ci * 48 + q * 4) = v;
    }
    __syncthreads();

    if (lane < 18) {
        int p0 = lane * 2;
        const float* sw = swgt + ty * 1152;
        unsigned long long acc01 = 0ull;
#pragma unroll 2
        for (int ci = 0; ci < 128; ci++) {
            const float2* s2 = (const float2*)(sbuf + ci * 48 + p0);
            float2 a0 = s2[0], a1 = s2[1], a2 = s2[2], a3 = s2[3], a4 = s2[4];
            unsigned long long P[9];
            P[0] = f2bits(a0); P[2] = f2bits(a1); P[4] = f2bits(a2);
            P[6] = f2bits(a3); P[8] = f2bits(a4);
            PACKF2(P[1], a0.y, a1.x);
            PACKF2(P[3], a1.y, a2.x);
            PACKF2(P[5], a2.y, a3.x);
            PACKF2(P[7], a3.y, a4.x);
            const float* wr = sw + ci * 9;
#pragma unroll
            for (int t = 0; t < 9; t++) {
                float wv = wr[t];
                unsigned long long W;
                PACKF2(W, wv, wv);
                FMAF2(acc01, W, P[t]);
            }
        }
        float o0, o1;
        UNPACKF2(o0, o1, acc01);
        float* cur = g_h2t + (size_t)co * N_TOT + b * 3600 + w_cur * 36 + p0;
        cur[0] += fmaxf(o0, 0.f);
        cur[1] += fmaxf(o1, 0.f);
    }
}

// ================= head =================
__global__ void conv2_k(const float* __restrict__ w2, const float* __restrict__ b2) {
    int nt = blockIdx.x * blockDim.x + threadIdx.x;
    if (nt >= N_TOT) return;
    int b = nt / 3600;
    int r = nt - b * 3600;
    int w = r / 36;
    int h = r - w * 36;
    int ns = b * 3600 + h * 100 + w;
    float acc[5];
#pragma unroll
    for (int c = 0; c < 5; c++) acc[c] = b2[c];
    for (int k = 0; k < 128; k++) {
        float xv = g_h2t[(size_t)k * N_TOT + nt];
#pragma unroll
        for (int c = 0; c < 5; c++)
            acc[c] = fmaf(__ldg(&w2[c * 128 + k]), xv, acc[c]);
    }
#pragma unroll
    for (int c = 0; c < 5; c++) g_h3[(size_t)c * N_TOT + ns] = acc[c];
}

__global__ void upsample_k(float* __restrict__ out) {
    int idx = blockIdx.x * blockDim.x + threadIdx.x;
    if (idx >= SEG_ELEMS) return;
    int ow = idx % 800;
    int t = idx / 800;
    int oh = t % 288; t /= 288;
    int c = t % 5;
    int b = t / 5;

    float fh = (float)oh * (35.0f / 287.0f);
    int i0 = (int)fh; if (i0 > 34) i0 = 34;
    float ah = fh - (float)i0;
    float fw = (float)ow * (99.0f / 799.0f);
    int j0 = (int)fw; if (j0 > 98) j0 = 98;
    float aw = fw - (float)j0;

    const float* src = g_h3 + (size_t)c * N_TOT + b * 3600;
    float v00 = src[i0 * 100 + j0];
    float v01 = src[i0 * 100 + j0 + 1];
    float v10 = src[(i0 + 1) * 100 + j0];
    float v11 = src[(i0 + 1) * 100 + j0 + 1];
    float xh0 = v00 * (1.f - ah) + v10 * ah;
    float xh1 = v01 * (1.f - ah) + v11 * ah;
    out[idx] = xh0 * (1.f - aw) + xh1 * aw;
}

__global__ void smpool_k() {
    int t = blockIdx.x * blockDim.x + threadIdx.x;
    if (t >= 8 * 18 * 50) return;
    int pw = t % 50;
    int r = t / 50;
    int ph = r % 18;
    int b = r / 18;

    float pc[5] = {0.f, 0.f, 0.f, 0.f, 0.f};
#pragma unroll
    for (int dh = 0; dh < 2; dh++)
#pragma unroll
        for (int dw = 0; dw < 2; dw++) {
            int h = 2 * ph + dh, w = 2 * pw + dw;
            const float* src = g_h3 + b * 3600 + h * 100 + w;
            float l[5];
#pragma unroll
            for (int c = 0; c < 5; c++) l[c] = src[(size_t)c * N_TOT];
            float mx = l[0];
#pragma unroll
            for (int c = 1; c < 5; c++) mx = fmaxf(mx, l[c]);
            float s = 0.f;
#pragma unroll
            for (int c = 0; c < 5; c++) { l[c] = expf(l[c] - mx); s += l[c]; }
            float inv = 1.f / s;
#pragma unroll
            for (int c = 0; c < 5; c++) pc[c] += l[c] * inv;
        }
#pragma unroll
    for (int c = 0; c < 5; c++)
        g_p[b * 4500 + c * 900 + ph * 50 + pw] = pc[c] * 0.25f;
}

__global__ void fc_k(const float* __restrict__ fc1w, const float* __restrict__ fc1b,
                     const float* __restrict__ fc2w, const float* __restrict__ fc2b,
                     float* __restrict__ out) {
    __shared__ float sf[128];
    int b = blockIdx.x;
    int c = threadIdx.x;
    const float* pb = g_p + b * 4500;
    float acc = fc1b[c];
    const float* wr = fc1w + c * 4500;
    for (int i = 0; i < 4500; i++)
        acc = fmaf(pb[i], wr[i], acc);
    sf[c] = fmaxf(acc, 0.f);
    __syncthreads();
    if (c < 4) {
        float a2 = fc2b[c];
#pragma unroll
        for (int k = 0; k < 128; k++)
            a2 = fmaf(sf[k], fc2w[c * 128 + k], a2);
        out[SEG_ELEMS + b * 4 + c] = 1.f / (1.f + expf(-a2));
    }
}

// ================= launch =================
extern "C" void kernel_launch(void* const* d_in, const int* in_sizes, int n_in,
                              void* d_out, int out_size) {
    const float* x    = (const float*)d_in[0];
    const float* w1a  = (const float*)d_in[1];
    const float* bn1g = (const float*)d_in[2];
    const float* bn1b = (const float*)d_in[3];
    const float* bn1m = (const float*)d_in[4];
    const float* bn1v = (const float*)d_in[5];
    const float* w1b  = (const float*)d_in[6];
    const float* bn2g = (const float*)d_in[7];
    const float* bn2b = (const float*)d_in[8];
    const float* bn2m = (const float*)d_in[9];
    const float* bn2v = (const float*)d_in[10];
    const float* wud  = (const float*)d_in[11];
    const float* wdu  = (const float*)d_in[12];
    const float* wlr  = (const float*)d_in[13];
    const float* wrl  = (const float*)d_in[14];
    const float* w2   = (const float*)d_in[15];
    const float* b2   = (const float*)d_in[16];
    const float* fc1w = (const float*)d_in[17];
    const float* fc1b = (const float*)d_in[18];
    const float* fc2w = (const float*)d_in[19];
    const float* fc2b = (const float*)d_in[20];
    float* out = (float*)d_out;

    cudaFuncSetAttribute(conv1a_mma, cudaFuncAttributeMaxDynamicSharedMemorySize, DSMEM1);
    cudaFuncSetAttribute(conv1b_mma, cudaFuncAttributeMaxDynamicSharedMemorySize, DSMEM2);
    cudaFuncSetAttribute(step_w4, cudaFuncAttributeMaxDynamicSharedMemorySize, 92160);
    cudaFuncSetAttribute(step_h4, cudaFuncAttributeMaxDynamicSharedMemorySize, 61440);

    // prep
    pack_w_k<<<(M1 * K1 + 255) / 256, 256>>>(w1a, w1b);
    transpose_k<<<dim3(900, 8), 256>>>(x);

    // stage 1 + 2: tensor-core GEMMs (fp16 2-term)
    conv1a_mma<<<dim3(225, 8), 256, DSMEM1>>>(bn1g, bn1b, bn1m, bn1v);
    conv1b_mma<<<dim3(225), 256, DSMEM2>>>(bn2g, bn2b, bn2m, bn2v);

    // w-scans
    for (int i = 1; i < 36; i++)  step_w4<<<dim3(8, 16), 256, 92160>>>(wud, i - 1, i);
    for (int i = 34; i >= 0; i--) step_w4<<<dim3(8, 16), 256, 92160>>>(wdu, i + 1, i);

    // transpose to [w][h] and run h-scans
    transpose_h2<<<dim3(128, 8), 256>>>();
    for (int j = 1; j < 100; j++) step_h4<<<dim3(8, 16), 256, 61440>>>(wlr, j - 1, j);
    for (int j = 98; j >= 0; j--) step_h4<<<dim3(8, 16), 256, 61440>>>(wrl, j + 1, j);

    // head
    conv2_k<<<(N_TOT + 255) / 256, 256>>>(w2, b2);
    upsample_k<<<(SEG_ELEMS + 255) / 256, 256>>>(out);
    smpool_k<<<(8 * 18 * 50 + 255) / 256, 256>>>();
    fc_k<<<8, 128>>>(fc1w, fc1b, fc2w, fc2b, out);
}

// round 14
// speedup vs baseline: 1.4819x; 1.4819x over previous
#include <cuda_runtime.h>
#include <cuda_bf16.h>
#include <cuda_fp16.h>
#include <cstdint>
#include <stdint.h>
#include <string.h>
#include <math.h>

// ---------------- problem constants ----------------
#define N_TOT   28800          // 8*36*100
#define K1      4608           // 512*9
#define M1      1024
#define K2      1024
#define M2      128
#define SEG_ELEMS (8*5*288*800)

// conv1a tiling: CTA 128m x 128n, K-chunk 32, double buffered, fp16 2-term
#define NCHUNK1 144
#define STG1A   24576          // Ahi 8K + Alo 8K + B 8K
#define DSMEM1 (2*STG1A)
// conv1b tiling: bf16 3-term (unchanged from R10)
#define NCHUNK2 32
#define STG1B   32768
#define A_LO_OFF  8192
#define B_HI_OFF 16384
#define B_LO_OFF 24576
#define DSMEM2 (2*STG1B)

// ---------------- device scratch ----------------
__device__ __half g_w1h[M1 * K1];             // conv1a W hi fp16 [m][k']
__device__ __half g_w1l[M1 * K1];             // conv1a W lo fp16
__device__ __half g_xt [N_TOT * 512];         // x transposed [n][c] fp16
__device__ __nv_bfloat16 g_w2h[M2 * K2];      // conv1b W hi bf16 [m][k]
__device__ __nv_bfloat16 g_w2l[M2 * K2];
__device__ __nv_bfloat16 g_h1h[M1 * N_TOT];   // h1 hi bf16 [k][n]
__device__ __nv_bfloat16 g_h1l[M1 * N_TOT];
__device__ __align__(16) unsigned char g_zerobuf[1024];
__device__ float g_h2 [M2 * N_TOT];   // [c][b][h][w]
__device__ float g_h2t[M2 * N_TOT];   // [c][b][w][h]
__device__ float g_h3[5 * N_TOT];
__device__ float g_p[8 * 4500];
// ---------------------------------------------------

// ================= PTX helpers =================
__device__ __forceinline__ uint32_t smem_u32(const void* p) {
    uint32_t a;
    asm("{ .reg .u64 t; cvta.to.shared.u64 t, %1; cvt.u32.u64 %0, t; }" : "=r"(a) : "l"(p));
    return a;
}
__device__ __forceinline__ void cp16(uint32_t dst, const void* src) {
    asm volatile("cp.async.cg.shared.global [%0], [%1], 16;" :: "r"(dst), "l"(src));
}
__device__ __forceinline__ void cp_commit() {
    asm volatile("cp.async.commit_group;");
}
template<int N> __device__ __forceinline__ void cp_wait() {
    asm volatile("cp.async.wait_group %0;" :: "n"(N) : "memory");
}
__device__ __forceinline__ void ldsm4(uint32_t addr, uint32_t r[4]) {
    asm volatile("ldmatrix.sync.aligned.m8n8.x4.shared.b16 {%0,%1,%2,%3}, [%4];"
                 : "=r"(r[0]), "=r"(r[1]), "=r"(r[2]), "=r"(r[3]) : "r"(addr));
}
__device__ __forceinline__ void ldsm4_t(uint32_t addr, uint32_t r[4]) {
    asm volatile("ldmatrix.sync.aligned.m8n8.x4.trans.shared.b16 {%0,%1,%2,%3}, [%4];"
                 : "=r"(r[0]), "=r"(r[1]), "=r"(r[2]), "=r"(r[3]) : "r"(addr));
}
// bf16 mma
__device__ __forceinline__ void mma_bf(float c[4], const uint32_t a[4], uint32_t b0, uint32_t b1) {
    asm volatile("mma.sync.aligned.m16n8k16.row.col.f32.bf16.bf16.f32 "
                 "{%0,%1,%2,%3}, {%4,%5,%6,%7}, {%8,%9}, {%0,%1,%2,%3};"
                 : "+f"(c[0]), "+f"(c[1]), "+f"(c[2]), "+f"(c[3])
                 : "r"(a[0]), "r"(a[1]), "r"(a[2]), "r"(a[3]), "r"(b0), "r"(b1));
}
// fp16 mma
__device__ __forceinline__ void mma_hf(float c[4], const uint32_t a[4], uint32_t b0, uint32_t b1) {
    asm volatile("mma.sync.aligned.m16n8k16.row.col.f32.f16.f16.f32 "
                 "{%0,%1,%2,%3}, {%4,%5,%6,%7}, {%8,%9}, {%0,%1,%2,%3};"
                 : "+f"(c[0]), "+f"(c[1]), "+f"(c[2]), "+f"(c[3])
                 : "r"(a[0]), "r"(a[1]), "r"(a[2]), "r"(a[3]), "r"(b0), "r"(b1));
}
// packed f32x2 ops
#define PACKF2(dst, lo, hi) asm("mov.b64 %0, {%1, %2};" : "=l"(dst) : "f"(lo), "f"(hi))
#define FMAF2(acc, a, bq)   asm("fma.rn.f32x2 %0, %1, %2, %0;" : "+l"(acc) : "l"(a), "l"(bq))
#define UNPACKF2(lo, hi, s) asm("mov.b64 {%0, %1}, %2;" : "=f"(lo), "=f"(hi) : "l"(s))
__device__ __forceinline__ unsigned long long f2bits(float2 v) {
    unsigned long long u;
    memcpy(&u, &v, 8);
    return u;
}

// ================= weight pack =================
__global__ void pack_w_k(const float* __restrict__ w1a, const float* __restrict__ w1b) {
    int o = blockIdx.x * blockDim.x + threadIdx.x;
    if (o < M1 * K1) {
        int m = o / K1;
        int k = o - m * K1;
        int tap = k >> 9;
        int c = k & 511;
        float v = w1a[(m * 512 + c) * 9 + tap];
        __half h = __float2half_rn(v);
        g_w1h[o] = h;
        g_w1l[o] = __float2half_rn(v - __half2float(h));
    }
    if (o < M2 * K2) {
        float v = w1b[o];
        __nv_bfloat16 h = __float2bfloat16(v);
        g_w2h[o] = h;
        g_w2l[o] = __float2bfloat16(v - __bfloat162float(h));
    }
}

// ================= x transpose: [b][c][hw] -> [n][c] fp16 =================
__global__ void transpose_k(const float* __restrict__ x) {
    __shared__ float t[32][65];
    int n0 = blockIdx.x * 32, c0 = blockIdx.y * 64;
    int tid = threadIdx.x;
#pragma unroll
    for (int i = 0; i < 8; i++) {
        int idx = tid + i * 256;
        int n_l = idx & 31, c_l = idx >> 5;
        int n = n0 + n_l;
        int b = n / 3600;
        int hw = n - b * 3600;
        t[n_l][c_l] = x[((size_t)(b * 512 + c0 + c_l)) * 3600 + hw];
    }
    __syncthreads();
#pragma unroll
    for (int i = 0; i < 8; i++) {
        int idx = tid + i * 256;
        int c_l = idx & 63, n_l = idx >> 6;
        g_xt[(size_t)(n0 + n_l) * 512 + c0 + c_l] = __float2half_rn(t[n_l][c_l]);
    }
}

// ================= conv1a: fp16 2-term implicit GEMM + BN1 + ReLU =================
// grid (225, 8); block 256 (8 warps: 4 m x 2 n); epilogue emits bf16 hi/lo h1 (as R10)
__global__ __launch_bounds__(256, 2)
void conv1a_mma(const float* __restrict__ bg, const float* __restrict__ bb,
                const float* __restrict__ bm, const float* __restrict__ bv) {
    extern __shared__ char dsm[];
    uint32_t dbase = smem_u32(dsm);

    int tid = threadIdx.x;
    int wid = tid >> 5;
    int lane = tid & 31;
    int n0 = blockIdx.x * 128;
    int m0 = blockIdx.y * 128;
    int wm = wid & 3;
    int wn = wid >> 2;

    int rA = tid >> 2;
    int gA = tid & 3;
    uint32_t dst1 = (uint32_t)(rA * 64 + ((gA ^ (rA & 3)) << 4));
    uint32_t dst2 = dst1 + 4096;

    const char* w1h_b = (const char*)g_w1h;
    const char* w1l_b = (const char*)g_w1l;
    size_t aoff1 = 2 * ((size_t)(m0 + rA) * K1 + gA * 8);
    size_t aoff2 = 2 * ((size_t)(m0 + rA + 64) * K1 + gA * 8);

    int nB1 = n0 + rA, nB2 = n0 + rA + 64;
    int b1 = nB1 / 3600, r1 = nB1 - b1 * 3600, h1_ = r1 / 100, w1_ = r1 - h1_ * 100;
    int b2 = nB2 / 3600, r2 = nB2 - b2 * 3600, h2_ = r2 / 100, w2_ = r2 - h2_ * 100;

    const char* bp1; const char* bp2;
    auto set_tap = [&](int tap) {
        int kh = tap / 3, kw = tap - kh * 3;
        int ih1 = h1_ + 4 * kh - 4, iw1 = w1_ + 4 * kw - 4;
        int ih2 = h2_ + 4 * kh - 4, iw2 = w2_ + 4 * kw - 4;
        bool v1 = ((unsigned)ih1 < 36u) && ((unsigned)iw1 < 100u);
        bool v2 = ((unsigned)ih2 < 36u) && ((unsigned)iw2 < 100u);
        size_t o1 = (size_t)(b1 * 3600 + ih1 * 100 + iw1) * 1024;
        size_t o2 = (size_t)(b2 * 3600 + ih2 * 100 + iw2) * 1024;
        bp1 = v1 ? (const char*)g_xt + o1 : (const char*)g_zerobuf;
        bp2 = v2 ? (const char*)g_xt + o2 : (const char*)g_zerobuf;
    };

    auto load_chunk = [&](int ch, int st) {
        uint32_t sb = dbase + st * STG1A;
        size_t k0b = (size_t)ch * 64;
        size_t cob = (size_t)(ch & 15) * 64 + gA * 16;
        cp16(sb + dst1, w1h_b + aoff1 + k0b);
        cp16(sb + dst2, w1h_b + aoff2 + k0b);
        cp16(sb + A_LO_OFF + dst1, w1l_b + aoff1 + k0b);
        cp16(sb + A_LO_OFF + dst2, w1l_b + aoff2 + k0b);
        cp16(sb + B_HI_OFF + dst1, bp1 + cob);
        cp16(sb + B_HI_OFF + dst2, bp2 + cob);
        cp_commit();
    };

    float acc[2][8][4];
#pragma unroll
    for (int f = 0; f < 2; f++)
#pragma unroll
        for (int nb = 0; nb < 8; nb++)
#pragma unroll
            for (int i = 0; i < 4; i++) acc[f][nb][i] = 0.f;

    int arow = wm * 32 + ((lane >> 3) & 1) * 8 + (lane & 7);
    int agl  = lane >> 4;
    int bnrow_base = wn * 64 + ((lane >> 4) & 1) * 8 + (lane & 7);
    int bgl = (lane >> 3) & 1;

    set_tap(0);
    load_chunk(0, 0);

    for (int ch = 0; ch < NCHUNK1; ch++) {
        int cur = ch & 1;
        if (ch + 1 < NCHUNK1) {
            if (((ch + 1) & 15) == 0) set_tap((ch + 1) >> 4);
            load_chunk(ch + 1, (ch + 1) & 1);
            cp_wait<1>();
        } else {
            cp_wait<0>();
        }
        __syncthreads();

        uint32_t sb = dbase + cur * STG1A;
#pragma unroll
        for (int s = 0; s < 2; s++) {
            uint32_t aH[2][4], aL[2][4];
#pragma unroll
            for (int f = 0; f < 2; f++) {
                int r = arow + f * 16;
                int g = 2 * s + agl;
                uint32_t off = (uint32_t)(r * 64 + ((g ^ (r & 3)) << 4));
                ldsm4(sb + off, aH[f]);
                ldsm4(sb + A_LO_OFF + off, aL[f]);
            }
            // q-pairs, term-major (same-acc distance 8)
#pragma unroll
            for (int qp = 0; qp < 2; qp++) {
                uint32_t bH[2][4];
#pragma unroll
                for (int j = 0; j < 2; j++) {
                    int nr = bnrow_base + (qp * 2 + j) * 16;
                    int g = 2 * s + bgl;
                    uint32_t off = (uint32_t)(nr * 64 + ((g ^ (nr & 3)) << 4));
                    ldsm4(sb + B_HI_OFF + off, bH[j]);
                }
#pragma unroll
                for (int j = 0; j < 2; j++) {
                    int q = qp * 2 + j;
#pragma unroll
                    for (int f = 0; f < 2; f++) {
                        mma_hf(acc[f][2 * q],     aH[f], bH[j][0], bH[j][1]);
                        mma_hf(acc[f][2 * q + 1], aH[f], bH[j][2], bH[j][3]);
                    }
                }
#pragma unroll
                for (int j = 0; j < 2; j++) {
                    int q = qp * 2 + j;
#pragma unroll
                    for (int f = 0; f < 2; f++) {
                        mma_hf(acc[f][2 * q],     aL[f], bH[j][0], bH[j][1]);
                        mma_hf(acc[f][2 * q + 1], aL[f], bH[j][2], bH[j][3]);
                    }
                }
            }
        }
        __syncthreads();
    }

    // epilogue: BN1 + ReLU -> bf16 hi/lo (identical to R10)
    int row0 = lane >> 2;
    int colp = (lane & 3) * 2;
#pragma unroll
    for (int f = 0; f < 2; f++) {
        int mA = m0 + wm * 32 + f * 16 + row0;
        int mB = mA + 8;
        float sA = bg[mA] * rsqrtf(bv[mA] + 1e-5f);
        float hA = bb[mA] - bm[mA] * sA;
        float sB = bg[mB] * rsqrtf(bv[mB] + 1e-5f);
        float hB = bb[mB] - bm[mB] * sB;
#pragma unroll
        for (int nb = 0; nb < 8; nb++) {
            int n = n0 + wn * 64 + nb * 8 + colp;
            float oa0 = fmaxf(fmaf(acc[f][nb][0], sA, hA), 0.f);
            float oa1 = fmaxf(fmaf(acc[f][nb][1], sA, hA), 0.f);
            float ob0 = fmaxf(fmaf(acc[f][nb][2], sB, hB), 0.f);
            float ob1 = fmaxf(fmaf(acc[f][nb][3], sB, hB), 0.f);
            __nv_bfloat162 hA2, lA2, hB2, lB2;
            hA2.x = __float2bfloat16(oa0); hA2.y = __float2bfloat16(oa1);
            lA2.x = __float2bfloat16(oa0 - __bfloat162float(hA2.x));
            lA2.y = __float2bfloat16(oa1 - __bfloat162float(hA2.y));
            hB2.x = __float2bfloat16(ob0); hB2.y = __float2bfloat16(ob1);
            lB2.x = __float2bfloat16(ob0 - __bfloat162float(hB2.x));
            lB2.y = __float2bfloat16(ob1 - __bfloat162float(hB2.y));
            *(__nv_bfloat162*)&g_h1h[(size_t)mA * N_TOT + n] = hA2;
            *(__nv_bfloat162*)&g_h1l[(size_t)mA * N_TOT + n] = lA2;
            *(__nv_bfloat162*)&g_h1h[(size_t)mB * N_TOT + n] = hB2;
            *(__nv_bfloat162*)&g_h1l[(size_t)mB * N_TOT + n] = lB2;
        }
    }
}

// ================= conv1b: bf16 3-term GEMM (EXACT R10) =================
__global__ __launch_bounds__(256, 2)
void conv1b_mma(const float* __restrict__ bg, const float* __restrict__ bb,
                const float* __restrict__ bm, const float* __restrict__ bv) {
    extern __shared__ char dsm2[];
    uint32_t dbase = smem_u32(dsm2);

    int tid = threadIdx.x;
    int wid = tid >> 5;
    int lane = tid & 31;
    int n0 = blockIdx.x * 128;
    int wm = wid & 3;
    int wn = wid >> 2;

    int rA = tid >> 2;
    int gA = tid & 3;
    uint32_t adst1 = (uint32_t)(rA * 64 + ((gA ^ (rA & 3)) << 4));
    uint32_t adst2 = adst1 + 4096;
    const char* w2h_b = (const char*)g_w2h;
    const char* w2l_b = (const char*)g_w2l;
    size_t aoff1 = (size_t)rA * 2048 + gA * 16;
    size_t aoff2 = (size_t)(rA + 64) * 2048 + gA * 16;

    const char* h1h_b = (const char*)g_h1h;
    const char* h1l_b = (const char*)g_h1l;
    uint32_t bdst[2]; size_t bsrc[2];
#pragma unroll
    for (int i = 0; i < 2; i++) {
        int idx = tid + i * 256;
        int k = idx >> 4, g = idx & 15;
        bdst[i] = (uint32_t)((k << 8) + ((g ^ (k & 7)) << 4));
        bsrc[i] = ((size_t)k * N_TOT + n0 + g * 8) * 2;
    }

    auto load_chunk = [&](int ch, int st) {
        uint32_t sb = dbase + st * STG1B;
        size_t ak = (size_t)ch * 64;
        size_t bk = (size_t)ch * 32 * N_TOT * 2;
        cp16(sb + adst1, w2h_b + aoff1 + ak);
        cp16(sb + adst2, w2h_b + aoff2 + ak);
        cp16(sb + A_LO_OFF + adst1, w2l_b + aoff1 + ak);
        cp16(sb + A_LO_OFF + adst2, w2l_b + aoff2 + ak);
        cp16(sb + B_HI_OFF + bdst[0], h1h_b + bk + bsrc[0]);
        cp16(sb + B_HI_OFF + bdst[1], h1h_b + bk + bsrc[1]);
        cp16(sb + B_LO_OFF + bdst[0], h1l_b + bk + bsrc[0]);
        cp16(sb + B_LO_OFF + bdst[1], h1l_b + bk + bsrc[1]);
        cp_commit();
    };

    float acc[2][8][4];
#pragma unroll
    for (int f = 0; f < 2; f++)
#pragma unroll
        for (int nb = 0; nb < 8; nb++)
#pragma unroll
            for (int i = 0; i < 4; i++) acc[f][nb][i] = 0.f;

    int arow = wm * 32 + ((lane >> 3) & 1) * 8 + (lane & 7);
    int agl  = lane >> 4;
    int bt = lane >> 3;
    int bkrow_base = (bt & 1) * 8 + (lane & 7);
    int bnc_base = wn * 8 + (bt >> 1);

    load_chunk(0, 0);

    for (int ch = 0; ch < NCHUNK2; ch++) {
        int cur = ch & 1;
        if (ch + 1 < NCHUNK2) {
            load_chunk(ch + 1, (ch + 1) & 1);
            cp_wait<1>();
        } else {
            cp_wait<0>();
        }
        __syncthreads();

        uint32_t sb = dbase + cur * STG1B;
#pragma unroll
        for (int s = 0; s < 2; s++) {
            uint32_t aH[2][4], aL[2][4];
#pragma unroll
            for (int f = 0; f < 2; f++) {
                int r = arow + f * 16;
                int g = 2 * s + agl;
                uint32_t off = (uint32_t)(r * 64 + ((g ^ (r & 3)) << 4));
                ldsm4(sb + off, aH[f]);
                ldsm4(sb + A_LO_OFF + off, aL[f]);
            }
#pragma unroll
            for (int q = 0; q < 4; q++) {
                int krow = s * 16 + bkrow_base;
                int ncol = bnc_base + q * 2;
                uint32_t off = (uint32_t)((krow << 8) + ((ncol ^ (krow & 7)) << 4));
                uint32_t bH[4], bL[4];
                ldsm4_t(sb + B_HI_OFF + off, bH);
                ldsm4_t(sb + B_LO_OFF + off, bL);
#pragma unroll
                for (int f = 0; f < 2; f++) {
                    mma_bf(acc[f][2 * q],     aH[f], bH[0], bH[1]);
                    mma_bf(acc[f][2 * q + 1], aH[f], bH[2], bH[3]);
                    mma_bf(acc[f][2 * q],     aL[f], bH[0], bH[1]);
                    mma_bf(acc[f][2 * q + 1], aL[f], bH[2], bH[3]);
                    mma_bf(acc[f][2 * q],     aH[f], bL[0], bL[1]);
                    mma_bf(acc[f][2 * q + 1], aH[f], bL[2], bL[3]);
                }
            }
        }
        __syncthreads();
    }

    int row0 = lane >> 2;
    int colp = (lane & 3) * 2;
#pragma unroll
    for (int f = 0; f < 2; f++) {
        int mA = wm * 32 + f * 16 + row0;
        int mB = mA + 8;
        float sA = bg[mA] * rsqrtf(bv[mA] + 1e-5f);
        float hA = bb[mA] - bm[mA] * sA;
        float sB = bg[mB] * rsqrtf(bv[mB] + 1e-5f);
        float hB = bb[mB] - bm[mB] * sB;
        float* dA = &g_h2[(size_t)mA * N_TOT];
        float* dB = &g_h2[(size_t)mB * N_TOT];
#pragma unroll
        for (int nb = 0; nb < 8; nb++) {
            int n = n0 + wn * 64 + nb * 8 + colp;
            float2 oa, ob;
            oa.x = fmaxf(fmaf(acc[f][nb][0], sA, hA), 0.f);
            oa.y = fmaxf(fmaf(acc[f][nb][1], sA, hA), 0.f);
            ob.x = fmaxf(fmaf(acc[f][nb][2], sB, hB), 0.f);
            ob.y = fmaxf(fmaf(acc[f][nb][3], sB, hB), 0.f);
            *(float2*)&dA[n] = oa;
            *(float2*)&dB[n] = ob;
        }
    }
}

// ================= message passing (EXACT R10: scalar staging + FFMA2) =================
__global__ __launch_bounds__(256)
void step_w4(const float* __restrict__ wgt, int h_prev, int h_cur) {
    extern __shared__ float sm[];
    float* swgt = sm;
    float* sbuf = sm + 9216;

    int tid = threadIdx.x;
    int lane = tid & 31, ty = tid >> 5;
    int b = blockIdx.x, cg = blockIdx.y;
    int co = cg * 8 + ty;

    const float* wsrc = wgt + cg * 8 * 1152;
    for (int i = tid; i < 9216; i += 256) swgt[i] = __ldg(&wsrc[i]);

    const float* prevBase = g_h2 + b * 3600 + h_prev * 100;
    for (int idx = tid; idx < 128 * 108; idx += 256) {
        int ci = idx / 108;
        int p = idx - ci * 108 - 4;
        sbuf[idx] = ((unsigned)p < 100u) ? prevBase[(size_t)ci * N_TOT + p] : 0.f;
    }
    __syncthreads();

    if (lane < 25) {
        int p0 = lane * 4;
        const float* sw = swgt + ty * 1152;
        unsigned long long acc01 = 0ull, acc23 = 0ull;
#pragma unroll 2
        for (int ci = 0; ci < 128; ci++) {
            const float2* s2 = (const float2*)(sbuf + ci * 108 + p0);
            float2 a0 = s2[0], a1 = s2[1], a2 = s2[2], a3 = s2[3], a4 = s2[4], a5 = s2[5];
            unsigned long long P[11];
            P[0] = f2bits(a0); P[2] = f2bits(a1); P[4] = f2bits(a2);
            P[6] = f2bits(a3); P[8] = f2bits(a4); P[10] = f2bits(a5);
            PACKF2(P[1], a0.y, a1.x);
            PACKF2(P[3], a1.y, a2.x);
            PACKF2(P[5], a2.y, a3.x);
            PACKF2(P[7], a3.y, a4.x);
            PACKF2(P[9], a4.y, a5.x);
            const float* wr = sw + ci * 9;
#pragma unroll
            for (int t = 0; t < 9; t++) {
                float wv = wr[t];
                unsigned long long W;
                PACKF2(W, wv, wv);
                FMAF2(acc01, W, P[t]);
                FMAF2(acc23, W, P[t + 2]);
            }
        }
        float o0, o1, o2, o3;
        UNPACKF2(o0, o1, acc01);
        UNPACKF2(o2, o3, acc23);
        float* cur = g_h2 + (size_t)co * N_TOT + b * 3600 + h_cur * 100 + p0;
        cur[0] += fmaxf(o0, 0.f);
        cur[1] += fmaxf(o1, 0.f);
        cur[2] += fmaxf(o2, 0.f);
        cur[3] += fmaxf(o3, 0.f);
    }
}

__global__ void transpose_h2() {
    __shared__ float sm[3600];
    int c = blockIdx.x, b = blockIdx.y;
    const float* src = g_h2 + (size_t)c * N_TOT + b * 3600;
    float* dst = g_h2t + (size_t)c * N_TOT + b * 3600;
    int tid = threadIdx.x;
    for (int i = tid; i < 3600; i += 256) sm[i] = src[i];
    __syncthreads();
    for (int j = tid; j < 3600; j += 256) {
        int w = j / 36, h = j - w * 36;
        dst[j] = sm[h * 100 + w];
    }
}

__global__ __launch_bounds__(256)
void step_h4(const float* __restrict__ wgt, int w_prev, int w_cur) {
    extern __shared__ float sm[];
    float* swgt = sm;
    float* sbuf = sm + 9216;

    int tid = threadIdx.x;
    int lane = tid & 31, ty = tid >> 5;
    int b = blockIdx.x, cg = blockIdx.y;
    int co = cg * 8 + ty;

    const float* wsrc = wgt + cg * 8 * 1152;
    for (int i = tid; i < 9216; i += 256) swgt[i] = __ldg(&wsrc[i]);

    const float* prevBase = g_h2t + b * 3600 + w_prev * 36;
    for (int idx = tid; idx < 128 * 44; idx += 256) {
        int ci = idx / 44;
        int s = idx - ci * 44;
        int p = s - 4;
        sbuf[ci * 48 + s] = ((unsigned)p < 36u) ? prevBase[(size_t)ci * N_TOT + p] : 0.f;
    }
    __syncthreads();

    if (lane < 18) {
        int p0 = lane * 2;
        const float* sw = swgt + ty * 1152;
        unsigned long long acc01 = 0ull;
#pragma unroll 2
        for (int ci = 0; ci < 128; ci++) {
            const float2* s2 = (const float2*)(sbuf + ci * 48 + p0);
            float2 a0 = s2[0], a1 = s2[1], a2 = s2[2], a3 = s2[3], a4 = s2[4];
            unsigned long long P[9];
            P[0] = f2bits(a0); P[2] = f2bits(a1); P[4] = f2bits(a2);
            P[6] = f2bits(a3); P[8] = f2bits(a4);
            PACKF2(P[1], a0.y, a1.x);
            PACKF2(P[3], a1.y, a2.x);
            PACKF2(P[5], a2.y, a3.x);
            PACKF2(P[7], a3.y, a4.x);
            const float* wr = sw + ci * 9;
#pragma unroll
            for (int t = 0; t < 9; t++) {
                float wv = wr[t];
                unsigned long long W;
                PACKF2(W, wv, wv);
                FMAF2(acc01, W, P[t]);
            }
        }
        float o0, o1;
        UNPACKF2(o0, o1, acc01);
        float* cur = g_h2t + (size_t)co * N_TOT + b * 3600 + w_cur * 36 + p0;
        cur[0] += fmaxf(o0, 0.f);
        cur[1] += fmaxf(o1, 0.f);
    }
}

// ================= head (unchanged) =================
__global__ void conv2_k(const float* __restrict__ w2, const float* __restrict__ b2) {
    int nt = blockIdx.x * blockDim.x + threadIdx.x;
    if (nt >= N_TOT) return;
    int b = nt / 3600;
    int r = nt - b * 3600;
    int w = r / 36;
    int h = r - w * 36;
    int ns = b * 3600 + h * 100 + w;
    float acc[5];
#pragma unroll
    for (int c = 0; c < 5; c++) acc[c] = b2[c];
    for (int k = 0; k < 128; k++) {
        float xv = g_h2t[(size_t)k * N_TOT + nt];
#pragma unroll
        for (int c = 0; c < 5; c++)
            acc[c] = fmaf(__ldg(&w2[c * 128 + k]), xv, acc[c]);
    }
#pragma unroll
    for (int c = 0; c < 5; c++) g_h3[(size_t)c * N_TOT + ns] = acc[c];
}

__global__ void upsample_k(float* __restrict__ out) {
    int idx = blockIdx.x * blockDim.x + threadIdx.x;
    if (idx >= SEG_ELEMS) return;
    int ow = idx % 800;
    int t = idx / 800;
    int oh = t % 288; t /= 288;
    int c = t % 5;
    int b = t / 5;

    float fh = (float)oh * (35.0f / 287.0f);
    int i0 = (int)fh; if (i0 > 34) i0 = 34;
    float ah = fh - (float)i0;
    float fw = (float)ow * (99.0f / 799.0f);
    int j0 = (int)fw; if (j0 > 98) j0 = 98;
    float aw = fw - (float)j0;

    const float* src = g_h3 + (size_t)c * N_TOT + b * 3600;
    float v00 = src[i0 * 100 + j0];
    float v01 = src[i0 * 100 + j0 + 1];
    float v10 = src[(i0 + 1) * 100 + j0];
    float v11 = src[(i0 + 1) * 100 + j0 + 1];
    float xh0 = v00 * (1.f - ah) + v10 * ah;
    float xh1 = v01 * (1.f - ah) + v11 * ah;
    out[idx] = xh0 * (1.f - aw) + xh1 * aw;
}

__global__ void smpool_k() {
    int t = blockIdx.x * blockDim.x + threadIdx.x;
    if (t >= 8 * 18 * 50) return;
    int pw = t % 50;
    int r = t / 50;
    int ph = r % 18;
    int b = r / 18;

    float pc[5] = {0.f, 0.f, 0.f, 0.f, 0.f};
#pragma unroll
    for (int dh = 0; dh < 2; dh++)
#pragma unroll
        for (int dw = 0; dw < 2; dw++) {
            int h = 2 * ph + dh, w = 2 * pw + dw;
            const float* src = g_h3 + b * 3600 + h * 100 + w;
            float l[5];
#pragma unroll
            for (int c = 0; c < 5; c++) l[c] = src[(size_t)c * N_TOT];
            float mx = l[0];
#pragma unroll
            for (int c = 1; c < 5; c++) mx = fmaxf(mx, l[c]);
            float s = 0.f;
#pragma unroll
            for (int c = 0; c < 5; c++) { l[c] = expf(l[c] - mx); s += l[c]; }
            float inv = 1.f / s;
#pragma unroll
            for (int c = 0; c < 5; c++) pc[c] += l[c] * inv;
        }
#pragma unroll
    for (int c = 0; c < 5; c++)
        g_p[b * 4500 + c * 900 + ph * 50 + pw] = pc[c] * 0.25f;
}

__global__ void fc_k(const float* __restrict__ fc1w, const float* __restrict__ fc1b,
                     const float* __restrict__ fc2w, const float* __restrict__ fc2b,
                     float* __restrict__ out) {
    __shared__ float sf[128];
    int b = blockIdx.x;
    int c = threadIdx.x;
    const float* pb = g_p + b * 4500;
    float acc = fc1b[c];
    const float* wr = fc1w + c * 4500;
    for (int i = 0; i < 4500; i++)
        acc = fmaf(pb[i], wr[i], acc);
    sf[c] = fmaxf(acc, 0.f);
    __syncthreads();
    if (c < 4) {
        float a2 = fc2b[c];
#pragma unroll
        for (int k = 0; k < 128; k++)
            a2 = fmaf(sf[k], fc2w[c * 128 + k], a2);
        out[SEG_ELEMS + b * 4 + c] = 1.f / (1.f + expf(-a2));
    }
}

// ================= launch =================
extern "C" void kernel_launch(void* const* d_in, const int* in_sizes, int n_in,
                              void* d_out, int out_size) {
    const float* x    = (const float*)d_in[0];
    const float* w1a  = (const float*)d_in[1];
    const float* bn1g = (const float*)d_in[2];
    const float* bn1b = (const float*)d_in[3];
    const float* bn1m = (const float*)d_in[4];
    const float* bn1v = (const float*)d_in[5];
    const float* w1b  = (const float*)d_in[6];
    const float* bn2g = (const float*)d_in[7];
    const float* bn2b = (const float*)d_in[8];
    const float* bn2m = (const float*)d_in[9];
    const float* bn2v = (const float*)d_in[10];
    const float* wud  = (const float*)d_in[11];
    const float* wdu  = (const float*)d_in[12];
    const float* wlr  = (const float*)d_in[13];
    const float* wrl  = (const float*)d_in[14];
    const float* w2   = (const float*)d_in[15];
    const float* b2   = (const float*)d_in[16];
    const float* fc1w = (const float*)d_in[17];
    const float* fc1b = (const float*)d_in[18];
    const float* fc2w = (const float*)d_in[19];
    const float* fc2b = (const float*)d_in[20];
    float* out = (float*)d_out;

    cudaFuncSetAttribute(conv1a_mma, cudaFuncAttributeMaxDynamicSharedMemorySize, DSMEM1);
    cudaFuncSetAttribute(conv1b_mma, cudaFuncAttributeMaxDynamicSharedMemorySize, DSMEM2);
    cudaFuncSetAttribute(step_w4, cudaFuncAttributeMaxDynamicSharedMemorySize, 92160);
    cudaFuncSetAttribute(step_h4, cudaFuncAttributeMaxDynamicSharedMemorySize, 61440);

    // prep
    pack_w_k<<<(M1 * K1 + 255) / 256, 256>>>(w1a, w1b);
    transpose_k<<<dim3(900, 8), 256>>>(x);

    // stage 1 (fp16 2-term) + stage 2 (bf16 3-term, R10)
    conv1a_mma<<<dim3(225, 8), 256, DSMEM1>>>(bn1g, bn1b, bn1m, bn1v);
    conv1b_mma<<<dim3(225), 256, DSMEM2>>>(bn2g, bn2b, bn2m, bn2v);

    // w-scans
    for (int i = 1; i < 36; i++)  step_w4<<<dim3(8, 16), 256, 92160>>>(wud, i - 1, i);
    for (int i = 34; i >= 0; i--) step_w4<<<dim3(8, 16), 256, 92160>>>(wdu, i + 1, i);

    // transpose to [w][h] and run h-scans
    transpose_h2<<<dim3(128, 8), 256>>>();
    for (int j = 1; j < 100; j++) step_h4<<<dim3(8, 16), 256, 61440>>>(wlr, j - 1, j);
    for (int j = 98; j >= 0; j--) step_h4<<<dim3(8, 16), 256, 61440>>>(wrl, j + 1, j);

    // head
    conv2_k<<<(N_TOT + 255) / 256, 256>>>(w2, b2);
    upsample_k<<<(SEG_ELEMS + 255) / 256, 256>>>(out);
    smpool_k<<<(8 * 18 * 50 + 255) / 256, 256>>>();
    fc_k<<<8, 128>>>(fc1w, fc1b, fc2w, fc2b, out);
}

// round 15
// speedup vs baseline: 1.5305x; 1.0328x over previous
#include <cuda_runtime.h>
#include <cuda_bf16.h>
#include <cuda_fp16.h>
#include <cstdint>
#include <stdint.h>
#include <string.h>
#include <math.h>

// ---------------- problem constants ----------------
#define N_TOT   28800          // 8*36*100
#define K1      4608           // 512*9
#define M1      1024
#define K2      1024
#define M2      128
#define SEG_ELEMS (8*5*288*800)

// conv1a tiling: CTA 128m x 128n, K-chunk 64, double buffered, fp16 2-term
#define NCHUNK1 72             // 4608/64
#define STG1A   49152          // Ahi 16K + Alo 16K + B 16K
#define A_LO_OFF1 16384
#define B_OFF1    32768
#define DSMEM1 (2*STG1A)
// conv1b tiling: bf16 3-term (unchanged from R10/R14)
#define NCHUNK2 32
#define STG1B   32768
#define A_LO_OFF  8192
#define B_HI_OFF 16384
#define B_LO_OFF 24576
#define DSMEM2 (2*STG1B)

// ---------------- device scratch ----------------
__device__ __half g_w1h[M1 * K1];             // conv1a W hi fp16 [m][k']
__device__ __half g_w1l[M1 * K1];             // conv1a W lo fp16
__device__ __half g_xt [N_TOT * 512];         // x transposed [n][c] fp16
__device__ __nv_bfloat16 g_w2h[M2 * K2];      // conv1b W hi bf16 [m][k]
__device__ __nv_bfloat16 g_w2l[M2 * K2];
__device__ __nv_bfloat16 g_h1h[M1 * N_TOT];   // h1 hi bf16 [k][n]
__device__ __nv_bfloat16 g_h1l[M1 * N_TOT];
__device__ __align__(16) unsigned char g_zerobuf[1024];
__device__ float g_h2 [M2 * N_TOT];   // [c][b][h][w]
__device__ float g_h2t[M2 * N_TOT];   // [c][b][w][h]
__device__ float g_h3[5 * N_TOT];
__device__ float g_p[8 * 4500];
// ---------------------------------------------------

// ================= PTX helpers =================
__device__ __forceinline__ uint32_t smem_u32(const void* p) {
    uint32_t a;
    asm("{ .reg .u64 t; cvta.to.shared.u64 t, %1; cvt.u32.u64 %0, t; }" : "=r"(a) : "l"(p));
    return a;
}
__device__ __forceinline__ void cp16(uint32_t dst, const void* src) {
    asm volatile("cp.async.cg.shared.global [%0], [%1], 16;" :: "r"(dst), "l"(src));
}
__device__ __forceinline__ void cp_commit() {
    asm volatile("cp.async.commit_group;");
}
template<int N> __device__ __forceinline__ void cp_wait() {
    asm volatile("cp.async.wait_group %0;" :: "n"(N) : "memory");
}
__device__ __forceinline__ void ldsm4(uint32_t addr, uint32_t r[4]) {
    asm volatile("ldmatrix.sync.aligned.m8n8.x4.shared.b16 {%0,%1,%2,%3}, [%4];"
                 : "=r"(r[0]), "=r"(r[1]), "=r"(r[2]), "=r"(r[3]) : "r"(addr));
}
__device__ __forceinline__ void ldsm4_t(uint32_t addr, uint32_t r[4]) {
    asm volatile("ldmatrix.sync.aligned.m8n8.x4.trans.shared.b16 {%0,%1,%2,%3}, [%4];"
                 : "=r"(r[0]), "=r"(r[1]), "=r"(r[2]), "=r"(r[3]) : "r"(addr));
}
// bf16 mma
__device__ __forceinline__ void mma_bf(float c[4], const uint32_t a[4], uint32_t b0, uint32_t b1) {
    asm volatile("mma.sync.aligned.m16n8k16.row.col.f32.bf16.bf16.f32 "
                 "{%0,%1,%2,%3}, {%4,%5,%6,%7}, {%8,%9}, {%0,%1,%2,%3};"
                 : "+f"(c[0]), "+f"(c[1]), "+f"(c[2]), "+f"(c[3])
                 : "r"(a[0]), "r"(a[1]), "r"(a[2]), "r"(a[3]), "r"(b0), "r"(b1));
}
// fp16 mma
__device__ __forceinline__ void mma_hf(float c[4], const uint32_t a[4], uint32_t b0, uint32_t b1) {
    asm volatile("mma.sync.aligned.m16n8k16.row.col.f32.f16.f16.f32 "
                 "{%0,%1,%2,%3}, {%4,%5,%6,%7}, {%8,%9}, {%0,%1,%2,%3};"
                 : "+f"(c[0]), "+f"(c[1]), "+f"(c[2]), "+f"(c[3])
                 : "r"(a[0]), "r"(a[1]), "r"(a[2]), "r"(a[3]), "r"(b0), "r"(b1));
}
// packed f32x2 ops
#define PACKF2(dst, lo, hi) asm("mov.b64 %0, {%1, %2};" : "=l"(dst) : "f"(lo), "f"(hi))
#define FMAF2(acc, a, bq)   asm("fma.rn.f32x2 %0, %1, %2, %0;" : "+l"(acc) : "l"(a), "l"(bq))
#define UNPACKF2(lo, hi, s) asm("mov.b64 {%0, %1}, %2;" : "=f"(lo), "=f"(hi) : "l"(s))
__device__ __forceinline__ unsigned long long f2bits(float2 v) {
    unsigned long long u;
    memcpy(&u, &v, 8);
    return u;
}

// ================= weight pack =================
__global__ void pack_w_k(const float* __restrict__ w1a, const float* __restrict__ w1b) {
    int o = blockIdx.x * blockDim.x + threadIdx.x;
    if (o < M1 * K1) {
        int m = o / K1;
        int k = o - m * K1;
        int tap = k >> 9;
        int c = k & 511;
        float v = w1a[(m * 512 + c) * 9 + tap];
        __half h = __float2half_rn(v);
        g_w1h[o] = h;
        g_w1l[o] = __float2half_rn(v - __half2float(h));
    }
    if (o < M2 * K2) {
        float v = w1b[o];
        __nv_bfloat16 h = __float2bfloat16(v);
        g_w2h[o] = h;
        g_w2l[o] = __float2bfloat16(v - __bfloat162float(h));
    }
}

// ================= x transpose: [b][c][hw] -> [n][c] fp16 =================
__global__ void transpose_k(const float* __restrict__ x) {
    __shared__ float t[32][65];
    int n0 = blockIdx.x * 32, c0 = blockIdx.y * 64;
    int tid = threadIdx.x;
#pragma unroll
    for (int i = 0; i < 8; i++) {
        int idx = tid + i * 256;
        int n_l = idx & 31, c_l = idx >> 5;
        int n = n0 + n_l;
        int b = n / 3600;
        int hw = n - b * 3600;
        t[n_l][c_l] = x[((size_t)(b * 512 + c0 + c_l)) * 3600 + hw];
    }
    __syncthreads();
#pragma unroll
    for (int i = 0; i < 8; i++) {
        int idx = tid + i * 256;
        int c_l = idx & 63, n_l = idx >> 6;
        g_xt[(size_t)(n0 + n_l) * 512 + c0 + c_l] = __float2half_rn(t[n_l][c_l]);
    }
}

// ================= conv1a: fp16 2-term, K-chunk 64, 128B-row swizzle =================
// grid (225, 8); block 256 (8 warps: 4 m x 2 n); epilogue emits bf16 hi/lo h1
__global__ __launch_bounds__(256, 2)
void conv1a_mma(const float* __restrict__ bg, const float* __restrict__ bb,
                const float* __restrict__ bm, const float* __restrict__ bv) {
    extern __shared__ char dsm[];
    uint32_t dbase = smem_u32(dsm);

    int tid = threadIdx.x;
    int wid = tid >> 5;
    int lane = tid & 31;
    int n0 = blockIdx.x * 128;
    int m0 = blockIdx.y * 128;
    int wm = wid & 3;
    int wn = wid >> 2;

    // loader: thread covers rows rA, rA+64 and granules gA, gA+4 (128B rows, 8 granules)
    int rA = tid >> 2;
    int gA = tid & 3;
    // swizzled dst offsets for (row, granule)
    uint32_t d_r1g1 = (uint32_t)(rA * 128 + (((gA)     ^ (rA & 7)) << 4));
    uint32_t d_r1g2 = (uint32_t)(rA * 128 + (((gA + 4) ^ (rA & 7)) << 4));
    uint32_t d_r2g1 = (uint32_t)((rA + 64) * 128 + (((gA)     ^ ((rA + 64) & 7)) << 4));
    uint32_t d_r2g2 = (uint32_t)((rA + 64) * 128 + (((gA + 4) ^ ((rA + 64) & 7)) << 4));

    const char* w1h_b = (const char*)g_w1h;
    const char* w1l_b = (const char*)g_w1l;
    size_t aBase1 = 2 * (size_t)(m0 + rA) * K1;
    size_t aBase2 = 2 * (size_t)(m0 + rA + 64) * K1;

    int nB1 = n0 + rA, nB2 = n0 + rA + 64;
    int b1 = nB1 / 3600, r1 = nB1 - b1 * 3600, h1_ = r1 / 100, w1_ = r1 - h1_ * 100;
    int b2 = nB2 / 3600, r2 = nB2 - b2 * 3600, h2_ = r2 / 100, w2_ = r2 - h2_ * 100;

    const char* bp1; const char* bp2;
    auto set_tap = [&](int tap) {
        int kh = tap / 3, kw = tap - kh * 3;
        int ih1 = h1_ + 4 * kh - 4, iw1 = w1_ + 4 * kw - 4;
        int ih2 = h2_ + 4 * kh - 4, iw2 = w2_ + 4 * kw - 4;
        bool v1 = ((unsigned)ih1 < 36u) && ((unsigned)iw1 < 100u);
        bool v2 = ((unsigned)ih2 < 36u) && ((unsigned)iw2 < 100u);
        size_t o1 = (size_t)(b1 * 3600 + ih1 * 100 + iw1) * 1024;
        size_t o2 = (size_t)(b2 * 3600 + ih2 * 100 + iw2) * 1024;
        bp1 = v1 ? (const char*)g_xt + o1 : (const char*)g_zerobuf;
        bp2 = v2 ? (const char*)g_xt + o2 : (const char*)g_zerobuf;
    };

    auto load_chunk = [&](int ch, int st) {
        uint32_t sb = dbase + st * STG1A;
        size_t ak = (size_t)ch * 128;                 // 64 fp16 = 128B per chunk along k
        size_t bk = (size_t)(ch & 7) * 128;           // within-tap channel offset (bytes)
        size_t g1 = (size_t)gA * 16, g2 = (size_t)(gA + 4) * 16;
        // A hi
        cp16(sb + d_r1g1, w1h_b + aBase1 + ak + g1);
        cp16(sb + d_r1g2, w1h_b + aBase1 + ak + g2);
        cp16(sb + d_r2g1, w1h_b + aBase2 + ak + g1);
        cp16(sb + d_r2g2, w1h_b + aBase2 + ak + g2);
        // A lo
        cp16(sb + A_LO_OFF1 + d_r1g1, w1l_b + aBase1 + ak + g1);
        cp16(sb + A_LO_OFF1 + d_r1g2, w1l_b + aBase1 + ak + g2);
        cp16(sb + A_LO_OFF1 + d_r2g1, w1l_b + aBase2 + ak + g1);
        cp16(sb + A_LO_OFF1 + d_r2g2, w1l_b + aBase2 + ak + g2);
        // B
        cp16(sb + B_OFF1 + d_r1g1, bp1 + bk + g1);
        cp16(sb + B_OFF1 + d_r1g2, bp1 + bk + g2);
        cp16(sb + B_OFF1 + d_r2g1, bp2 + bk + g1);
        cp16(sb + B_OFF1 + d_r2g2, bp2 + bk + g2);
        cp_commit();
    };

    float acc[2][8][4];
#pragma unroll
    for (int f = 0; f < 2; f++)
#pragma unroll
        for (int nb = 0; nb < 8; nb++)
#pragma unroll
            for (int i = 0; i < 4; i++) acc[f][nb][i] = 0.f;

    int arow = wm * 32 + ((lane >> 3) & 1) * 8 + (lane & 7);
    int agl  = lane >> 4;               // 0/1
    int bnrow_base = wn * 64 + ((lane >> 4) & 1) * 8 + (lane & 7);
    int bgl = (lane >> 3) & 1;

    set_tap(0);
    load_chunk(0, 0);

    for (int ch = 0; ch < NCHUNK1; ch++) {
        int cur = ch & 1;
        if (ch + 1 < NCHUNK1) {
            if (((ch + 1) & 7) == 0) set_tap((ch + 1) >> 3);
            load_chunk(ch + 1, (ch + 1) & 1);
            cp_wait<1>();
        } else {
            cp_wait<0>();
        }
        __syncthreads();

        uint32_t sb = dbase + cur * STG1A;
#pragma unroll
        for (int s = 0; s < 4; s++) {
            uint32_t aH[2][4], aL[2][4];
#pragma unroll
            for (int f = 0; f < 2; f++) {
                int r = arow + f * 16;
                int g = 2 * s + agl;
                uint32_t off = (uint32_t)(r * 128 + ((g ^ (r & 7)) << 4));
                ldsm4(sb + off, aH[f]);
                ldsm4(sb + A_LO_OFF1 + off, aL[f]);
            }
            // q-pairs, term-major (same-acc distance 8)
#pragma unroll
            for (int qp = 0; qp < 2; qp++) {
                uint32_t bH[2][4];
#pragma unroll
                for (int j = 0; j < 2; j++) {
                    int nr = bnrow_base + (qp * 2 + j) * 16;
                    int g = 2 * s + bgl;
                    uint32_t off = (uint32_t)(nr * 128 + ((g ^ (nr & 7)) << 4));
                    ldsm4(sb + B_OFF1 + off, bH[j]);
                }
#pragma unroll
                for (int j = 0; j < 2; j++) {
                    int q = qp * 2 + j;
#pragma unroll
                    for (int f = 0; f < 2; f++) {
                        mma_hf(acc[f][2 * q],     aH[f], bH[j][0], bH[j][1]);
                        mma_hf(acc[f][2 * q + 1], aH[f], bH[j][2], bH[j][3]);
                    }
                }
#pragma unroll
                for (int j = 0; j < 2; j++) {
                    int q = qp * 2 + j;
#pragma unroll
                    for (int f = 0; f < 2; f++) {
                        mma_hf(acc[f][2 * q],     aL[f], bH[j][0], bH[j][1]);
                        mma_hf(acc[f][2 * q + 1], aL[f], bH[j][2], bH[j][3]);
                    }
                }
            }
        }
        __syncthreads();
    }

    // epilogue: BN1 + ReLU -> bf16 hi/lo (identical to R14)
    int row0 = lane >> 2;
    int colp = (lane & 3) * 2;
#pragma unroll
    for (int f = 0; f < 2; f++) {
        int mA = m0 + wm * 32 + f * 16 + row0;
        int mB = mA + 8;
        float sA = bg[mA] * rsqrtf(bv[mA] + 1e-5f);
        float hA = bb[mA] - bm[mA] * sA;
        float sB = bg[mB] * rsqrtf(bv[mB] + 1e-5f);
        float hB = bb[mB] - bm[mB] * sB;
#pragma unroll
        for (int nb = 0; nb < 8; nb++) {
            int n = n0 + wn * 64 + nb * 8 + colp;
            float oa0 = fmaxf(fmaf(acc[f][nb][0], sA, hA), 0.f);
            float oa1 = fmaxf(fmaf(acc[f][nb][1], sA, hA), 0.f);
            float ob0 = fmaxf(fmaf(acc[f][nb][2], sB, hB), 0.f);
            float ob1 = fmaxf(fmaf(acc[f][nb][3], sB, hB), 0.f);
            __nv_bfloat162 hA2, lA2, hB2, lB2;
            hA2.x = __float2bfloat16(oa0); hA2.y = __float2bfloat16(oa1);
            lA2.x = __float2bfloat16(oa0 - __bfloat162float(hA2.x));
            lA2.y = __float2bfloat16(oa1 - __bfloat162float(hA2.y));
            hB2.x = __float2bfloat16(ob0); hB2.y = __float2bfloat16(ob1);
            lB2.x = __float2bfloat16(ob0 - __bfloat162float(hB2.x));
            lB2.y = __float2bfloat16(ob1 - __bfloat162float(hB2.y));
            *(__nv_bfloat162*)&g_h1h[(size_t)mA * N_TOT + n] = hA2;
            *(__nv_bfloat162*)&g_h1l[(size_t)mA * N_TOT + n] = lA2;
            *(__nv_bfloat162*)&g_h1h[(size_t)mB * N_TOT + n] = hB2;
            *(__nv_bfloat162*)&g_h1l[(size_t)mB * N_TOT + n] = lB2;
        }
    }
}

// ================= conv1b: bf16 3-term GEMM (EXACT R14) =================
__global__ __launch_bounds__(256, 2)
void conv1b_mma(const float* __restrict__ bg, const float* __restrict__ bb,
                const float* __restrict__ bm, const float* __restrict__ bv) {
    extern __shared__ char dsm2[];
    uint32_t dbase = smem_u32(dsm2);

    int tid = threadIdx.x;
    int wid = tid >> 5;
    int lane = tid & 31;
    int n0 = blockIdx.x * 128;
    int wm = wid & 3;
    int wn = wid >> 2;

    int rA = tid >> 2;
    int gA = tid & 3;
    uint32_t adst1 = (uint32_t)(rA * 64 + ((gA ^ (rA & 3)) << 4));
    uint32_t adst2 = adst1 + 4096;
    const char* w2h_b = (const char*)g_w2h;
    const char* w2l_b = (const char*)g_w2l;
    size_t aoff1 = (size_t)rA * 2048 + gA * 16;
    size_t aoff2 = (size_t)(rA + 64) * 2048 + gA * 16;

    const char* h1h_b = (const char*)g_h1h;
    const char* h1l_b = (const char*)g_h1l;
    uint32_t bdst[2]; size_t bsrc[2];
#pragma unroll
    for (int i = 0; i < 2; i++) {
        int idx = tid + i * 256;
        int k = idx >> 4, g = idx & 15;
        bdst[i] = (uint32_t)((k << 8) + ((g ^ (k & 7)) << 4));
        bsrc[i] = ((size_t)k * N_TOT + n0 + g * 8) * 2;
    }

    auto load_chunk = [&](int ch, int st) {
        uint32_t sb = dbase + st * STG1B;
        size_t ak = (size_t)ch * 64;
        size_t bk = (size_t)ch * 32 * N_TOT * 2;
        cp16(sb + adst1, w2h_b + aoff1 + ak);
        cp16(sb + adst2, w2h_b + aoff2 + ak);
        cp16(sb + A_LO_OFF + adst1, w2l_b + aoff1 + ak);
        cp16(sb + A_LO_OFF + adst2, w2l_b + aoff2 + ak);
        cp16(sb + B_HI_OFF + bdst[0], h1h_b + bk + bsrc[0]);
        cp16(sb + B_HI_OFF + bdst[1], h1h_b + bk + bsrc[1]);
        cp16(sb + B_LO_OFF + bdst[0], h1l_b + bk + bsrc[0]);
        cp16(sb + B_LO_OFF + bdst[1], h1l_b + bk + bsrc[1]);
        cp_commit();
    };

    float acc[2][8][4];
#pragma unroll
    for (int f = 0; f < 2; f++)
#pragma unroll
        for (int nb = 0; nb < 8; nb++)
#pragma unroll
            for (int i = 0; i < 4; i++) acc[f][nb][i] = 0.f;

    int arow = wm * 32 + ((lane >> 3) & 1) * 8 + (lane & 7);
    int agl  = lane >> 4;
    int bt = lane >> 3;
    int bkrow_base = (bt & 1) * 8 + (lane & 7);
    int bnc_base = wn * 8 + (bt >> 1);

    load_chunk(0, 0);

    for (int ch = 0; ch < NCHUNK2; ch++) {
        int cur = ch & 1;
        if (ch + 1 < NCHUNK2) {
            load_chunk(ch + 1, (ch + 1) & 1);
            cp_wait<1>();
        } else {
            cp_wait<0>();
        }
        __syncthreads();

        uint32_t sb = dbase + cur * STG1B;
#pragma unroll
        for (int s = 0; s < 2; s++) {
            uint32_t aH[2][4], aL[2][4];
#pragma unroll
            for (int f = 0; f < 2; f++) {
                int r = arow + f * 16;
                int g = 2 * s + agl;
                uint32_t off = (uint32_t)(r * 64 + ((g ^ (r & 3)) << 4));
                ldsm4(sb + off, aH[f]);
                ldsm4(sb + A_LO_OFF + off, aL[f]);
            }
#pragma unroll
            for (int q = 0; q < 4; q++) {
                int krow = s * 16 + bkrow_base;
                int ncol = bnc_base + q * 2;
                uint32_t off = (uint32_t)((krow << 8) + ((ncol ^ (krow & 7)) << 4));
                uint32_t bH[4], bL[4];
                ldsm4_t(sb + B_HI_OFF + off, bH);
                ldsm4_t(sb + B_LO_OFF + off, bL);
#pragma unroll
                for (int f = 0; f < 2; f++) {
                    mma_bf(acc[f][2 * q],     aH[f], bH[0], bH[1]);
                    mma_bf(acc[f][2 * q + 1], aH[f], bH[2], bH[3]);
                    mma_bf(acc[f][2 * q],     aL[f], bH[0], bH[1]);
                    mma_bf(acc[f][2 * q + 1], aL[f], bH[2], bH[3]);
                    mma_bf(acc[f][2 * q],     aH[f], bL[0], bL[1]);
                    mma_bf(acc[f][2 * q + 1], aH[f], bL[2], bL[3]);
                }
            }
        }
        __syncthreads();
    }

    int row0 = lane >> 2;
    int colp = (lane & 3) * 2;
#pragma unroll
    for (int f = 0; f < 2; f++) {
        int mA = wm * 32 + f * 16 + row0;
        int mB = mA + 8;
        float sA = bg[mA] * rsqrtf(bv[mA] + 1e-5f);
        float hA = bb[mA] - bm[mA] * sA;
        float sB = bg[mB] * rsqrtf(bv[mB] + 1e-5f);
        float hB = bb[mB] - bm[mB] * sB;
        float* dA = &g_h2[(size_t)mA * N_TOT];
        float* dB = &g_h2[(size_t)mB * N_TOT];
#pragma unroll
        for (int nb = 0; nb < 8; nb++) {
            int n = n0 + wn * 64 + nb * 8 + colp;
            float2 oa, ob;
            oa.x = fmaxf(fmaf(acc[f][nb][0], sA, hA), 0.f);
            oa.y = fmaxf(fmaf(acc[f][nb][1], sA, hA), 0.f);
            ob.x = fmaxf(fmaf(acc[f][nb][2], sB, hB), 0.f);
            ob.y = fmaxf(fmaf(acc[f][nb][3], sB, hB), 0.f);
            *(float2*)&dA[n] = oa;
            *(float2*)&dB[n] = ob;
        }
    }
}

// ================= message passing (EXACT R14) =================
__global__ __launch_bounds__(256)
void step_w4(const float* __restrict__ wgt, int h_prev, int h_cur) {
    extern __shared__ float sm[];
    float* swgt = sm;
    float* sbuf = sm + 9216;

    int tid = threadIdx.x;
    int lane = tid & 31, ty = tid >> 5;
    int b = blockIdx.x, cg = blockIdx.y;
    int co = cg * 8 + ty;

    const float* wsrc = wgt + cg * 8 * 1152;
    for (int i = tid; i < 9216; i += 256) swgt[i] = __ldg(&wsrc[i]);

    const float* prevBase = g_h2 + b * 3600 + h_prev * 100;
    for (int idx = tid; idx < 128 * 108; idx += 256) {
        int ci = idx / 108;
        int p = idx - ci * 108 - 4;
        sbuf[idx] = ((unsigned)p < 100u) ? prevBase[(size_t)ci * N_TOT + p] : 0.f;
    }
    __syncthreads();

    if (lane < 25) {
        int p0 = lane * 4;
        const float* sw = swgt + ty * 1152;
        unsigned long long acc01 = 0ull, acc23 = 0ull;
#pragma unroll 2
        for (int ci = 0; ci < 128; ci++) {
            const float2* s2 = (const float2*)(sbuf + ci * 108 + p0);
            float2 a0 = s2[0], a1 = s2[1], a2 = s2[2], a3 = s2[3], a4 = s2[4], a5 = s2[5];
            unsigned long long P[11];
            P[0] = f2bits(a0); P[2] = f2bits(a1); P[4] = f2bits(a2);
            P[6] = f2bits(a3); P[8] = f2bits(a4); P[10] = f2bits(a5);
            PACKF2(P[1], a0.y, a1.x);
            PACKF2(P[3], a1.y, a2.x);
            PACKF2(P[5], a2.y, a3.x);
            PACKF2(P[7], a3.y, a4.x);
            PACKF2(P[9], a4.y, a5.x);
            const float* wr = sw + ci * 9;
#pragma unroll
            for (int t = 0; t < 9; t++) {
                float wv = wr[t];
                unsigned long long W;
                PACKF2(W, wv, wv);
                FMAF2(acc01, W, P[t]);
                FMAF2(acc23, W, P[t + 2]);
            }
        }
        float o0, o1, o2, o3;
        UNPACKF2(o0, o1, acc01);
        UNPACKF2(o2, o3, acc23);
        float* cur = g_h2 + (size_t)co * N_TOT + b * 3600 + h_cur * 100 + p0;
        cur[0] += fmaxf(o0, 0.f);
        cur[1] += fmaxf(o1, 0.f);
        cur[2] += fmaxf(o2, 0.f);
        cur[3] += fmaxf(o3, 0.f);
    }
}

__global__ void transpose_h2() {
    __shared__ float sm[3600];
    int c = blockIdx.x, b = blockIdx.y;
    const float* src = g_h2 + (size_t)c * N_TOT + b * 3600;
    float* dst = g_h2t + (size_t)c * N_TOT + b * 3600;
    int tid = threadIdx.x;
    for (int i = tid; i < 3600; i += 256) sm[i] = src[i];
    __syncthreads();
    for (int j = tid; j < 3600; j += 256) {
        int w = j / 36, h = j - w * 36;
        dst[j] = sm[h * 100 + w];
    }
}

__global__ __launch_bounds__(256)
void step_h4(const float* __restrict__ wgt, int w_prev, int w_cur) {
    extern __shared__ float sm[];
    float* swgt = sm;
    float* sbuf = sm + 9216;

    int tid = threadIdx.x;
    int lane = tid & 31, ty = tid >> 5;
    int b = blockIdx.x, cg = blockIdx.y;
    int co = cg * 8 + ty;

    const float* wsrc = wgt + cg * 8 * 1152;
    for (int i = tid; i < 9216; i += 256) swgt[i] = __ldg(&wsrc[i]);

    const float* prevBase = g_h2t + b * 3600 + w_prev * 36;
    for (int idx = tid; idx < 128 * 44; idx += 256) {
        int ci = idx / 44;
        int s = idx - ci * 44;
        int p = s - 4;
        sbuf[ci * 48 + s] = ((unsigned)p < 36u) ? prevBase[(size_t)ci * N_TOT + p] : 0.f;
    }
    __syncthreads();

    if (lane < 18) {
        int p0 = lane * 2;
        const float* sw = swgt + ty * 1152;
        unsigned long long acc01 = 0ull;
#pragma unroll 2
        for (int ci = 0; ci < 128; ci++) {
            const float2* s2 = (const float2*)(sbuf + ci * 48 + p0);
            float2 a0 = s2[0], a1 = s2[1], a2 = s2[2], a3 = s2[3], a4 = s2[4];
            unsigned long long P[9];
            P[0] = f2bits(a0); P[2] = f2bits(a1); P[4] = f2bits(a2);
            P[6] = f2bits(a3); P[8] = f2bits(a4);
            PACKF2(P[1], a0.y, a1.x);
            PACKF2(P[3], a1.y, a2.x);
            PACKF2(P[5], a2.y, a3.x);
            PACKF2(P[7], a3.y, a4.x);
            const float* wr = sw + ci * 9;
#pragma unroll
            for (int t = 0; t < 9; t++) {
                float wv = wr[t];
                unsigned long long W;
                PACKF2(W, wv, wv);
                FMAF2(acc01, W, P[t]);
            }
        }
        float o0, o1;
        UNPACKF2(o0, o1, acc01);
        float* cur = g_h2t + (size_t)co * N_TOT + b * 3600 + w_cur * 36 + p0;
        cur[0] += fmaxf(o0, 0.f);
        cur[1] += fmaxf(o1, 0.f);
    }
}

// ================= head (unchanged) =================
__global__ void conv2_k(const float* __restrict__ w2, const float* __restrict__ b2) {
    int nt = blockIdx.x * blockDim.x + threadIdx.x;
    if (nt >= N_TOT) return;
    int b = nt / 3600;
    int r = nt - b * 3600;
    int w = r / 36;
    int h = r - w * 36;
    int ns = b * 3600 + h * 100 + w;
    float acc[5];
#pragma unroll
    for (int c = 0; c < 5; c++) acc[c] = b2[c];
    for (int k = 0; k < 128; k++) {
        float xv = g_h2t[(size_t)k * N_TOT + nt];
#pragma unroll
        for (int c = 0; c < 5; c++)
            acc[c] = fmaf(__ldg(&w2[c * 128 + k]), xv, acc[c]);
    }
#pragma unroll
    for (int c = 0; c < 5; c++) g_h3[(size_t)c * N_TOT + ns] = acc[c];
}

__global__ void upsample_k(float* __restrict__ out) {
    int idx = blockIdx.x * blockDim.x + threadIdx.x;
    if (idx >= SEG_ELEMS) return;
    int ow = idx % 800;
    int t = idx / 800;
    int oh = t % 288; t /= 288;
    int c = t % 5;
    int b = t / 5;

    float fh = (float)oh * (35.0f / 287.0f);
    int i0 = (int)fh; if (i0 > 34) i0 = 34;
    float ah = fh - (float)i0;
    float fw = (float)ow * (99.0f / 799.0f);
    int j0 = (int)fw; if (j0 > 98) j0 = 98;
    float aw = fw - (float)j0;

    const float* src = g_h3 + (size_t)c * N_TOT + b * 3600;
    float v00 = src[i0 * 100 + j0];
    float v01 = src[i0 * 100 + j0 + 1];
    float v10 = src[(i0 + 1) * 100 + j0];
    float v11 = src[(i0 + 1) * 100 + j0 + 1];
    float xh0 = v00 * (1.f - ah) + v10 * ah;
    float xh1 = v01 * (1.f - ah) + v11 * ah;
    out[idx] = xh0 * (1.f - aw) + xh1 * aw;
}

__global__ void smpool_k() {
    int t = blockIdx.x * blockDim.x + threadIdx.x;
    if (t >= 8 * 18 * 50) return;
    int pw = t % 50;
    int r = t / 50;
    int ph = r % 18;
    int b = r / 18;

    float pc[5] = {0.f, 0.f, 0.f, 0.f, 0.f};
#pragma unroll
    for (int dh = 0; dh < 2; dh++)
#pragma unroll
        for (int dw = 0; dw < 2; dw++) {
            int h = 2 * ph + dh, w = 2 * pw + dw;
            const float* src = g_h3 + b * 3600 + h * 100 + w;
            float l[5];
#pragma unroll
            for (int c = 0; c < 5; c++) l[c] = src[(size_t)c * N_TOT];
            float mx = l[0];
#pragma unroll
            for (int c = 1; c < 5; c++) mx = fmaxf(mx, l[c]);
            float s = 0.f;
#pragma unroll
            for (int c = 0; c < 5; c++) { l[c] = expf(l[c] - mx); s += l[c]; }
            float inv = 1.f / s;
#pragma unroll
            for (int c = 0; c < 5; c++) pc[c] += l[c] * inv;
        }
#pragma unroll
    for (int c = 0; c < 5; c++)
        g_p[b * 4500 + c * 900 + ph * 50 + pw] = pc[c] * 0.25f;
}

__global__ void fc_k(const float* __restrict__ fc1w, const float* __restrict__ fc1b,
                     const float* __restrict__ fc2w, const float* __restrict__ fc2b,
                     float* __restrict__ out) {
    __shared__ float sf[128];
    int b = blockIdx.x;
    int c = threadIdx.x;
    const float* pb = g_p + b * 4500;
    float acc = fc1b[c];
    const float* wr = fc1w + c * 4500;
    for (int i = 0; i < 4500; i++)
        acc = fmaf(pb[i], wr[i], acc);
    sf[c] = fmaxf(acc, 0.f);
    __syncthreads();
    if (c < 4) {
        float a2 = fc2b[c];
#pragma unroll
        for (int k = 0; k < 128; k++)
            a2 = fmaf(sf[k], fc2w[c * 128 + k], a2);
        out[SEG_ELEMS + b * 4 + c] = 1.f / (1.f + expf(-a2));
    }
}

// ================= launch =================
extern "C" void kernel_launch(void* const* d_in, const int* in_sizes, int n_in,
                              void* d_out, int out_size) {
    const float* x    = (const float*)d_in[0];
    const float* w1a  = (const float*)d_in[1];
    const float* bn1g = (const float*)d_in[2];
    const float* bn1b = (const float*)d_in[3];
    const float* bn1m = (const float*)d_in[4];
    const float* bn1v = (const float*)d_in[5];
    const float* w1b  = (const float*)d_in[6];
    const float* bn2g = (const float*)d_in[7];
    const float* bn2b = (const float*)d_in[8];
    const float* bn2m = (const float*)d_in[9];
    const float* bn2v = (const float*)d_in[10];
    const float* wud  = (const float*)d_in[11];
    const float* wdu  = (const float*)d_in[12];
    const float* wlr  = (const float*)d_in[13];
    const float* wrl  = (const float*)d_in[14];
    const float* w2   = (const float*)d_in[15];
    const float* b2   = (const float*)d_in[16];
    const float* fc1w = (const float*)d_in[17];
    const float* fc1b = (const float*)d_in[18];
    const float* fc2w = (const float*)d_in[19];
    const float* fc2b = (const float*)d_in[20];
    float* out = (float*)d_out;

    cudaFuncSetAttribute(conv1a_mma, cudaFuncAttributeMaxDynamicSharedMemorySize, DSMEM1);
    cudaFuncSetAttribute(conv1b_mma, cudaFuncAttributeMaxDynamicSharedMemorySize, DSMEM2);
    cudaFuncSetAttribute(step_w4, cudaFuncAttributeMaxDynamicSharedMemorySize, 92160);
    cudaFuncSetAttribute(step_h4, cudaFuncAttributeMaxDynamicSharedMemorySize, 61440);

    // prep
    pack_w_k<<<(M1 * K1 + 255) / 256, 256>>>(w1a, w1b);
    transpose_k<<<dim3(900, 8), 256>>>(x);

    // stage 1 (fp16 2-term, K64) + stage 2 (bf16 3-term)
    conv1a_mma<<<dim3(225, 8), 256, DSMEM1>>>(bn1g, bn1b, bn1m, bn1v);
    conv1b_mma<<<dim3(225), 256, DSMEM2>>>(bn2g, bn2b, bn2m, bn2v);

    // w-scans
    for (int i = 1; i < 36; i++)  step_w4<<<dim3(8, 16), 256, 92160>>>(wud, i - 1, i);
    for (int i = 34; i >= 0; i--) step_w4<<<dim3(8, 16), 256, 92160>>>(wdu, i + 1, i);

    // transpose to [w][h] and run h-scans
    transpose_h2<<<dim3(128, 8), 256>>>();
    for (int j = 1; j < 100; j++) step_h4<<<dim3(8, 16), 256, 61440>>>(wlr, j - 1, j);
    for (int j = 98; j >= 0; j--) step_h4<<<dim3(8, 16), 256, 61440>>>(wrl, j + 1, j);

    // head
    conv2_k<<<(N_TOT + 255) / 256, 256>>>(w2, b2);
    upsample_k<<<(SEG_ELEMS + 255) / 256, 256>>>(out);
    smpool_k<<<(8 * 18 * 50 + 255) / 256, 256>>>();
    fc_k<<<8, 128>>>(fc1w, fc1b, fc2w, fc2b, out);
}